// round 4
// baseline (speedup 1.0000x reference)
#include <cuda_runtime.h>
#include <cuda_bf16.h>
#include <cstdint>
#include <cstddef>

#define NN 50000
#define EE 850000
#define HH 4

// ---------------- scratch (static device globals; no runtime alloc) ----------
__device__ float g_h[(size_t)NN * 256];       // current layer h = x @ W (fp32)
__device__ float g_el[NN * HH];
__device__ float g_er[NN * HH];
__device__ int   g_indeg[NN];
__device__ int   g_off[NN + 1];
__device__ int   g_cur[NN];
__device__ int   g_eidx[EE];
__device__ __nv_bfloat16 g_Ahi[(size_t)NN * 256];  // GEMM input split-hi
__device__ __nv_bfloat16 g_Alo[(size_t)NN * 256];  // GEMM input split-lo
__device__ __nv_bfloat16 g_Wthi[256 * 256];   // W split-hi, transposed [n][k]
__device__ __nv_bfloat16 g_Wtlo[256 * 256];   // W split-lo, transposed [n][k]

// ---------------- PTX helpers (sm_80-era only; no arch-suffix features) ------
__device__ __forceinline__ uint32_t smem_u32(const void* p) {
    uint32_t a;
    asm("{ .reg .u64 t; cvta.to.shared.u64 t, %1; cvt.u32.u64 %0, t; }"
        : "=r"(a) : "l"(p));
    return a;
}
#define CP_ASYNC16(dst, src) \
    asm volatile("cp.async.cg.shared.global [%0], [%1], 16;" :: "r"(dst), "l"(src))
#define CP_COMMIT() asm volatile("cp.async.commit_group;" ::: "memory")
#define CP_WAIT(n)  asm volatile("cp.async.wait_group %0;" :: "n"(n) : "memory")

__device__ __forceinline__ void mma_bf16(float* c, const uint32_t* a,
                                         uint32_t b0, uint32_t b1) {
    asm volatile(
        "mma.sync.aligned.m16n8k16.row.col.f32.bf16.bf16.f32 "
        "{%0,%1,%2,%3}, {%4,%5,%6,%7}, {%8,%9}, {%0,%1,%2,%3};"
        : "+f"(c[0]), "+f"(c[1]), "+f"(c[2]), "+f"(c[3])
        : "r"(a[0]), "r"(a[1]), "r"(a[2]), "r"(a[3]), "r"(b0), "r"(b1));
}

// ---------------- CSR build ----------------
__global__ void zero_indeg_kernel() {
    int i = blockIdx.x * blockDim.x + threadIdx.x;
    if (i < NN) g_indeg[i] = 0;
}

__global__ void csr_count_kernel(const int* __restrict__ dst, int E) {
    int e = blockIdx.x * blockDim.x + threadIdx.x;
    if (e < E) atomicAdd(&g_indeg[dst[e]], 1);
}

__global__ void scan_kernel() {
    __shared__ int warp_sums[32];
    __shared__ int s_carry;
    int tid = threadIdx.x;
    int lane = tid & 31, wid = tid >> 5;
    if (tid == 0) s_carry = 0;
    __syncthreads();
    for (int base = 0; base < NN; base += 1024) {
        int idx = base + tid;
        int v = (idx < NN) ? g_indeg[idx] : 0;
        int x = v;
        #pragma unroll
        for (int o = 1; o < 32; o <<= 1) {
            int t = __shfl_up_sync(0xffffffffu, x, o);
            if (lane >= o) x += t;
        }
        if (lane == 31) warp_sums[wid] = x;
        __syncthreads();
        if (wid == 0) {
            int ws = warp_sums[lane];
            #pragma unroll
            for (int o = 1; o < 32; o <<= 1) {
                int t = __shfl_up_sync(0xffffffffu, ws, o);
                if (lane >= o) ws += t;
            }
            warp_sums[lane] = ws;
        }
        __syncthreads();
        int warp_excl = (wid == 0) ? 0 : warp_sums[wid - 1];
        int excl = x - v + warp_excl + s_carry;
        if (idx < NN) { g_off[idx] = excl; g_cur[idx] = excl; }
        __syncthreads();
        if (tid == 0) s_carry += warp_sums[31];
        __syncthreads();
    }
    if (threadIdx.x == 0) g_off[NN] = s_carry;
}

__global__ void csr_scatter_kernel(const int* __restrict__ dst, int E) {
    int e = blockIdx.x * blockDim.x + threadIdx.x;
    if (e < E) {
        int p = atomicAdd(&g_cur[dst[e]], 1);
        g_eidx[p] = e;
    }
}

// ---------------- splits ----------------
__global__ void wsplit_kernel(const float* __restrict__ W) {
    int idx = blockIdx.x * 256 + threadIdx.x;     // 65536 elements
    int k = idx >> 8, n = idx & 255;
    float v = W[k * 256 + n];
    __nv_bfloat16 hi = __float2bfloat16_rn(v);
    __nv_bfloat16 lo = __float2bfloat16_rn(v - __bfloat162float(hi));
    g_Wthi[n * 256 + k] = hi;
    g_Wtlo[n * 256 + k] = lo;
}

__global__ void asplit_kernel(const float* __restrict__ X) {
    size_t i = (size_t)blockIdx.x * 256 + threadIdx.x;
    float v = X[i];
    __nv_bfloat16 hi = __float2bfloat16_rn(v);
    __nv_bfloat16 lo = __float2bfloat16_rn(v - __bfloat162float(hi));
    g_Ahi[i] = hi;
    g_Alo[i] = lo;
}

// --------- bf16x3 mma.sync GEMM, cp.async double-buffered --------------------
// C[nrows,256] = (Ahi+Alo) @ (Whi+Wlo)^T using hi*hi + hi*lo + lo*hi.
// BM=128, BN=128, BK=32; 256 threads = 8 warps (4m x 2n), warp tile 32m x 64n.
#define SA 40                              // bf16 elements per smem row (80 B)
#define ATILE (128 * SA)                   // one A/B array = 5120 bf16 = 10240 B
#define BUFSZ (4 * ATILE)                  // Ah,Al,Bh,Bl
#define GEMM_SMEM (2 * BUFSZ * 2)          // 2 buffers, bytes (2*40960=81920)

__global__ __launch_bounds__(256) void gemm_mma_kernel(
    const __nv_bfloat16* __restrict__ Ahi, const __nv_bfloat16* __restrict__ Alo,
    float* __restrict__ C, int nrows)
{
    extern __shared__ __nv_bfloat16 sm[];   // [2][4][ATILE]
    int tid = threadIdx.x;
    int lane = tid & 31;
    int wid = tid >> 5;
    int wm = wid & 3, wn = wid >> 2;
    int g = lane >> 2, t = lane & 3;
    int rowBase = blockIdx.x * 128;
    int nbase = blockIdx.y * 128;

    uint32_t sb = smem_u32(sm);

    float acc[2][8][4];
    #pragma unroll
    for (int mt = 0; mt < 2; mt++)
        #pragma unroll
        for (int nt = 0; nt < 8; nt++)
            #pragma unroll
            for (int q = 0; q < 4; q++) acc[mt][nt][q] = 0.f;

    // staging lambda (macro-style): thread handles chunks tid and tid+256 of
    // 512 (128 rows x 4 16B-chunks) for each of A and B.
    #define STAGE(buf, k0)                                                        \
    do {                                                                          \
        uint32_t base = sb + (uint32_t)(buf) * (BUFSZ * 2);                       \
        _Pragma("unroll")                                                         \
        for (int p = 0; p < 2; p++) {                                             \
            int c = tid + p * 256;                                                \
            int r = c >> 2, j = c & 3;                                            \
            uint32_t so = (uint32_t)(r * (SA * 2) + j * 16);                      \
            int arow = rowBase + r;                                               \
            if (arow < nrows) {                                                   \
                const __nv_bfloat16* ga = Ahi + (size_t)arow * 256 + (k0) + j * 8;\
                const __nv_bfloat16* gb = Alo + (size_t)arow * 256 + (k0) + j * 8;\
                CP_ASYNC16(base + so, ga);                                        \
                CP_ASYNC16(base + ATILE * 2 + so, gb);                            \
            }                                                                     \
            const __nv_bfloat16* gh = g_Wthi + (size_t)(nbase + r) * 256 + (k0) + j * 8; \
            const __nv_bfloat16* gl = g_Wtlo + (size_t)(nbase + r) * 256 + (k0) + j * 8; \
            CP_ASYNC16(base + ATILE * 4 + so, gh);                                \
            CP_ASYNC16(base + ATILE * 6 + so, gl);                                \
        }                                                                         \
        CP_COMMIT();                                                              \
    } while (0)

    STAGE(0, 0);

    #pragma unroll
    for (int kt = 0; kt < 8; kt++) {
        if (kt < 7) STAGE((kt + 1) & 1, (kt + 1) * 32);
        if (kt < 7) { CP_WAIT(1); } else { CP_WAIT(0); }
        __syncthreads();

        const __nv_bfloat16* Ash = sm + (kt & 1) * BUFSZ;
        const __nv_bfloat16* Asl = Ash + ATILE;
        const __nv_bfloat16* Bsh = Asl + ATILE;
        const __nv_bfloat16* Bsl = Bsh + ATILE;

        #pragma unroll
        for (int kk = 0; kk < 2; kk++) {
            int ks = kk * 16;
            uint32_t ah[2][4], al[2][4];
            #pragma unroll
            for (int mt = 0; mt < 2; mt++) {
                int r0 = (wm * 32 + mt * 16 + g) * SA;
                int r1 = r0 + 8 * SA;
                ah[mt][0] = *(const uint32_t*)&Ash[r0 + ks + 2 * t];
                ah[mt][1] = *(const uint32_t*)&Ash[r1 + ks + 2 * t];
                ah[mt][2] = *(const uint32_t*)&Ash[r0 + ks + 2 * t + 8];
                ah[mt][3] = *(const uint32_t*)&Ash[r1 + ks + 2 * t + 8];
                al[mt][0] = *(const uint32_t*)&Asl[r0 + ks + 2 * t];
                al[mt][1] = *(const uint32_t*)&Asl[r1 + ks + 2 * t];
                al[mt][2] = *(const uint32_t*)&Asl[r0 + ks + 2 * t + 8];
                al[mt][3] = *(const uint32_t*)&Asl[r1 + ks + 2 * t + 8];
            }
            #pragma unroll
            for (int nt = 0; nt < 8; nt++) {
                int nb = (wn * 64 + nt * 8 + g) * SA;
                uint32_t bh0 = *(const uint32_t*)&Bsh[nb + ks + 2 * t];
                uint32_t bh1 = *(const uint32_t*)&Bsh[nb + ks + 2 * t + 8];
                uint32_t bl0 = *(const uint32_t*)&Bsl[nb + ks + 2 * t];
                uint32_t bl1 = *(const uint32_t*)&Bsl[nb + ks + 2 * t + 8];
                #pragma unroll
                for (int mt = 0; mt < 2; mt++) {
                    mma_bf16(acc[mt][nt], ah[mt], bh0, bh1);
                    mma_bf16(acc[mt][nt], ah[mt], bl0, bl1);
                    mma_bf16(acc[mt][nt], al[mt], bh0, bh1);
                }
            }
        }
        __syncthreads();
    }

    // epilogue
    #pragma unroll
    for (int mt = 0; mt < 2; mt++) {
        int r0 = rowBase + wm * 32 + mt * 16 + g;
        int r1 = r0 + 8;
        #pragma unroll
        for (int nt = 0; nt < 8; nt++) {
            int col = nbase + wn * 64 + nt * 8 + 2 * t;
            if (r0 < nrows)
                *(float2*)(C + (size_t)r0 * 256 + col) =
                    make_float2(acc[mt][nt][0], acc[mt][nt][1]);
            if (r1 < nrows)
                *(float2*)(C + (size_t)r1 * 256 + col) =
                    make_float2(acc[mt][nt][2], acc[mt][nt][3]);
        }
    }
}

// ---------------- per-node attention coefs: el/er ----------------
__global__ __launch_bounds__(256) void attn_kernel(
    const float* __restrict__ h, const float* __restrict__ al,
    const float* __restrict__ ar)
{
    int n = blockIdx.x;
    int tid = threadIdx.x;
    float v = h[(size_t)n * 256 + tid];
    float pl = v * al[tid];
    float pr = v * ar[tid];
    #pragma unroll
    for (int o = 16; o > 0; o >>= 1) {
        pl += __shfl_xor_sync(0xffffffffu, pl, o);
        pr += __shfl_xor_sync(0xffffffffu, pr, o);
    }
    __shared__ float sl[8], sr[8];
    int wid = tid >> 5;
    if ((tid & 31) == 0) { sl[wid] = pl; sr[wid] = pr; }
    __syncthreads();
    if (tid < 4) {
        g_el[n * 4 + tid] = sl[2 * tid] + sl[2 * tid + 1];
        g_er[n * 4 + tid] = sr[2 * tid] + sr[2 * tid + 1];
    }
}

// ---------- fused edge-softmax + CSR aggregation ----------
__global__ __launch_bounds__(256) void aggregate_kernel(
    const float* __restrict__ hbuf, const int* __restrict__ src,
    const float* __restrict__ bias, float* __restrict__ outf, int write_bf16)
{
    int n = blockIdx.x;
    int tid = threadIdx.x;
    int hh = tid >> 6;
    int beg = g_off[n], end = g_off[n + 1];

    __shared__ int   s_src[128];
    __shared__ float s_a[128 * 4];

    float4 rn = ((const float4*)g_er)[n];
    float acc = 0.f, den = 0.f;

    for (int base = beg; base < end; base += 128) {
        int cnt = min(128, end - base);
        __syncthreads();
        for (int i = tid; i < cnt; i += 256) {
            int eid = g_eidx[base + i];
            int s = src[eid];
            s_src[i] = s;
            float4 l = ((const float4*)g_el)[s];
            float4 w;
            float e0 = l.x + rn.x; e0 = (e0 > 0.f) ? e0 : 0.2f * e0; w.x = __expf(e0);
            float e1 = l.y + rn.y; e1 = (e1 > 0.f) ? e1 : 0.2f * e1; w.y = __expf(e1);
            float e2 = l.z + rn.z; e2 = (e2 > 0.f) ? e2 : 0.2f * e2; w.z = __expf(e2);
            float e3 = l.w + rn.w; e3 = (e3 > 0.f) ? e3 : 0.2f * e3; w.w = __expf(e3);
            ((float4*)s_a)[i] = w;
        }
        __syncthreads();
        int i = 0;
        for (; i + 4 <= cnt; i += 4) {
            float a0 = s_a[(i + 0) * 4 + hh];
            float a1 = s_a[(i + 1) * 4 + hh];
            float a2 = s_a[(i + 2) * 4 + hh];
            float a3 = s_a[(i + 3) * 4 + hh];
            int s0 = s_src[i], s1 = s_src[i + 1], s2 = s_src[i + 2], s3 = s_src[i + 3];
            float h0 = hbuf[(size_t)s0 * 256 + tid];
            float h1 = hbuf[(size_t)s1 * 256 + tid];
            float h2 = hbuf[(size_t)s2 * 256 + tid];
            float h3 = hbuf[(size_t)s3 * 256 + tid];
            acc += a0 * h0 + a1 * h1 + a2 * h2 + a3 * h3;
            den += (a0 + a1) + (a2 + a3);
        }
        for (; i < cnt; i++) {
            float a = s_a[i * 4 + hh];
            acc += a * hbuf[(size_t)s_src[i] * 256 + tid];
            den += a;
        }
    }
    float v = fmaxf(acc / den + bias[tid], 0.f);
    size_t oi = (size_t)n * 256 + tid;
    if (write_bf16) {
        __nv_bfloat16 hi = __float2bfloat16_rn(v);
        __nv_bfloat16 lo = __float2bfloat16_rn(v - __bfloat162float(hi));
        g_Ahi[oi] = hi;
        g_Alo[oi] = lo;
    } else {
        outf[oi] = v;
    }
}

// ---------------- launch ----------------
extern "C" void kernel_launch(void* const* d_in, const int* in_sizes, int n_in,
                              void* d_out, int out_size)
{
    const float* feat = (const float*)d_in[0];
    const int*   src  = (const int*)d_in[1];
    const int*   dst  = (const int*)d_in[2];
    const float* W1   = (const float*)d_in[3];
    const float* al1  = (const float*)d_in[4];
    const float* ar1  = (const float*)d_in[5];
    const float* b1   = (const float*)d_in[6];
    const float* W2   = (const float*)d_in[7];
    const float* al2  = (const float*)d_in[8];
    const float* ar2  = (const float*)d_in[9];
    const float* b2   = (const float*)d_in[10];
    float* out = (float*)d_out;
    int E = in_sizes[1];

    void* p;
    cudaGetSymbolAddress(&p, g_h);   float* h   = (float*)p;
    cudaGetSymbolAddress(&p, g_Ahi); __nv_bfloat16* ahi = (__nv_bfloat16*)p;
    cudaGetSymbolAddress(&p, g_Alo); __nv_bfloat16* alo = (__nv_bfloat16*)p;

    static int smem_set = 0;
    if (!smem_set) {
        cudaFuncSetAttribute(gemm_mma_kernel,
                             cudaFuncAttributeMaxDynamicSharedMemorySize, GEMM_SMEM);
        smem_set = 1;
    }

    int egrid = (E + 255) / 256;
    int ngrid = (NN + 255) / 256;
    dim3 ggrid((NN + 127) / 128, 2);

    // CSR build (same for both layers)
    zero_indeg_kernel<<<ngrid, 256>>>();
    csr_count_kernel<<<egrid, 256>>>(dst, E);
    scan_kernel<<<1, 1024>>>();
    csr_scatter_kernel<<<egrid, 256>>>(dst, E);

    // layer 1
    asplit_kernel<<<NN, 256>>>(feat);
    wsplit_kernel<<<256, 256>>>(W1);
    gemm_mma_kernel<<<ggrid, 256, GEMM_SMEM>>>(ahi, alo, h, NN);
    attn_kernel<<<NN, 256>>>(h, al1, ar1);
    aggregate_kernel<<<NN, 256>>>(h, src, b1, nullptr, 1);

    // layer 2
    wsplit_kernel<<<256, 256>>>(W2);
    gemm_mma_kernel<<<ggrid, 256, GEMM_SMEM>>>(ahi, alo, h, NN);
    attn_kernel<<<NN, 256>>>(h, al2, ar2);
    aggregate_kernel<<<NN, 256>>>(h, src, b2, out, 0);
}

// round 5
// speedup vs baseline: 1.5098x; 1.5098x over previous
#include <cuda_runtime.h>
#include <cuda_bf16.h>
#include <cuda_fp16.h>
#include <cstdint>
#include <cstddef>

#define NN 50000
#define EE 850000
#define HH 4

// ---------------- scratch (static device globals; no runtime alloc) ----------
__device__ __half g_hh[(size_t)NN * 256];     // h in fp16 (gather table)
__device__ float g_el[NN * HH];
__device__ float g_er[NN * HH];
__device__ int   g_indeg[NN];
__device__ int   g_off[NN + 1];
__device__ int   g_cur[NN];
__device__ int   g_eidx[EE];
__device__ __nv_bfloat16 g_Ahi[(size_t)NN * 256];  // GEMM input split-hi
__device__ __nv_bfloat16 g_Alo[(size_t)NN * 256];  // GEMM input split-lo
__device__ __nv_bfloat16 g_Wthi[256 * 256];   // W split-hi, transposed [n][k]
__device__ __nv_bfloat16 g_Wtlo[256 * 256];   // W split-lo, transposed [n][k]

// ---------------- PTX helpers ----------------
__device__ __forceinline__ uint32_t smem_u32(const void* p) {
    uint32_t a;
    asm("{ .reg .u64 t; cvta.to.shared.u64 t, %1; cvt.u32.u64 %0, t; }"
        : "=r"(a) : "l"(p));
    return a;
}
#define CP_ASYNC16(dst, src) \
    asm volatile("cp.async.cg.shared.global [%0], [%1], 16;" :: "r"(dst), "l"(src))
#define CP_COMMIT() asm volatile("cp.async.commit_group;" ::: "memory")
#define CP_WAIT(n)  asm volatile("cp.async.wait_group %0;" :: "n"(n) : "memory")

__device__ __forceinline__ void mma_bf16(float* c, const uint32_t* a,
                                         uint32_t b0, uint32_t b1) {
    asm volatile(
        "mma.sync.aligned.m16n8k16.row.col.f32.bf16.bf16.f32 "
        "{%0,%1,%2,%3}, {%4,%5,%6,%7}, {%8,%9}, {%0,%1,%2,%3};"
        : "+f"(c[0]), "+f"(c[1]), "+f"(c[2]), "+f"(c[3])
        : "r"(a[0]), "r"(a[1]), "r"(a[2]), "r"(a[3]), "r"(b0), "r"(b1));
}

// ---------------- CSR build ----------------
__global__ void zero_indeg_kernel() {
    int i = blockIdx.x * blockDim.x + threadIdx.x;
    if (i < NN) g_indeg[i] = 0;
}

__global__ void csr_count_kernel(const int* __restrict__ dst, int E) {
    int e = blockIdx.x * blockDim.x + threadIdx.x;
    if (e < E) atomicAdd(&g_indeg[dst[e]], 1);
}

__global__ void scan_kernel() {
    __shared__ int warp_sums[32];
    __shared__ int s_carry;
    int tid = threadIdx.x;
    int lane = tid & 31, wid = tid >> 5;
    if (tid == 0) s_carry = 0;
    __syncthreads();
    for (int base = 0; base < NN; base += 1024) {
        int idx = base + tid;
        int v = (idx < NN) ? g_indeg[idx] : 0;
        int x = v;
        #pragma unroll
        for (int o = 1; o < 32; o <<= 1) {
            int t = __shfl_up_sync(0xffffffffu, x, o);
            if (lane >= o) x += t;
        }
        if (lane == 31) warp_sums[wid] = x;
        __syncthreads();
        if (wid == 0) {
            int ws = warp_sums[lane];
            #pragma unroll
            for (int o = 1; o < 32; o <<= 1) {
                int t = __shfl_up_sync(0xffffffffu, ws, o);
                if (lane >= o) ws += t;
            }
            warp_sums[lane] = ws;
        }
        __syncthreads();
        int warp_excl = (wid == 0) ? 0 : warp_sums[wid - 1];
        int excl = x - v + warp_excl + s_carry;
        if (idx < NN) { g_off[idx] = excl; g_cur[idx] = excl; }
        __syncthreads();
        if (tid == 0) s_carry += warp_sums[31];
        __syncthreads();
    }
    if (threadIdx.x == 0) g_off[NN] = s_carry;
}

__global__ void csr_scatter_kernel(const int* __restrict__ dst, int E) {
    int e = blockIdx.x * blockDim.x + threadIdx.x;
    if (e < E) {
        int p = atomicAdd(&g_cur[dst[e]], 1);
        g_eidx[p] = e;
    }
}

// ---------------- splits ----------------
__global__ void wsplit_kernel(const float* __restrict__ W) {
    int idx = blockIdx.x * 256 + threadIdx.x;     // 65536 elements
    int k = idx >> 8, n = idx & 255;
    float v = W[k * 256 + n];
    __nv_bfloat16 hi = __float2bfloat16_rn(v);
    __nv_bfloat16 lo = __float2bfloat16_rn(v - __bfloat162float(hi));
    g_Wthi[n * 256 + k] = hi;
    g_Wtlo[n * 256 + k] = lo;
}

__global__ void asplit_kernel(const float* __restrict__ X) {
    size_t i = (size_t)blockIdx.x * 256 + threadIdx.x;
    float v = X[i];
    __nv_bfloat16 hi = __float2bfloat16_rn(v);
    __nv_bfloat16 lo = __float2bfloat16_rn(v - __bfloat162float(hi));
    g_Ahi[i] = hi;
    g_Alo[i] = lo;
}

// --------- bf16x3 mma.sync GEMM + fused attn epilogue -----------------------
// h[n][256] = (Ahi+Alo)@(Whi+Wlo)^T -> written fp16 to g_hh
// el[n][head] = sum_d h*al, er likewise -> written directly (no atomics):
// warp wn owns head 2*by+wn entirely (64 cols), rows unique per thread group.
#define SA 40
#define ATILE (128 * SA)
#define BUFSZ (4 * ATILE)
#define GEMM_SMEM (2 * BUFSZ * 2)

__global__ __launch_bounds__(256) void gemm_mma_kernel(
    const __nv_bfloat16* __restrict__ Ahi, const __nv_bfloat16* __restrict__ Alo,
    const float* __restrict__ al, const float* __restrict__ ar, int nrows)
{
    extern __shared__ __nv_bfloat16 sm[];
    int tid = threadIdx.x;
    int lane = tid & 31;
    int wid = tid >> 5;
    int wm = wid & 3, wn = wid >> 2;
    int g = lane >> 2, t = lane & 3;
    int rowBase = blockIdx.x * 128;
    int nbase = blockIdx.y * 128;

    uint32_t sb = smem_u32(sm);

    float acc[2][8][4];
    #pragma unroll
    for (int mt = 0; mt < 2; mt++)
        #pragma unroll
        for (int nt = 0; nt < 8; nt++)
            #pragma unroll
            for (int q = 0; q < 4; q++) acc[mt][nt][q] = 0.f;

    #define STAGE(buf, k0)                                                        \
    do {                                                                          \
        uint32_t base = sb + (uint32_t)(buf) * (BUFSZ * 2);                       \
        _Pragma("unroll")                                                         \
        for (int p = 0; p < 2; p++) {                                             \
            int c = tid + p * 256;                                                \
            int r = c >> 2, j = c & 3;                                            \
            uint32_t so = (uint32_t)(r * (SA * 2) + j * 16);                      \
            int arow = rowBase + r;                                               \
            if (arow < nrows) {                                                   \
                const __nv_bfloat16* ga = Ahi + (size_t)arow * 256 + (k0) + j * 8;\
                const __nv_bfloat16* gb = Alo + (size_t)arow * 256 + (k0) + j * 8;\
                CP_ASYNC16(base + so, ga);                                        \
                CP_ASYNC16(base + ATILE * 2 + so, gb);                            \
            }                                                                     \
            const __nv_bfloat16* gh = g_Wthi + (size_t)(nbase + r) * 256 + (k0) + j * 8; \
            const __nv_bfloat16* gl = g_Wtlo + (size_t)(nbase + r) * 256 + (k0) + j * 8; \
            CP_ASYNC16(base + ATILE * 4 + so, gh);                                \
            CP_ASYNC16(base + ATILE * 6 + so, gl);                                \
        }                                                                         \
        CP_COMMIT();                                                              \
    } while (0)

    STAGE(0, 0);

    #pragma unroll
    for (int kt = 0; kt < 8; kt++) {
        if (kt < 7) STAGE((kt + 1) & 1, (kt + 1) * 32);
        if (kt < 7) { CP_WAIT(1); } else { CP_WAIT(0); }
        __syncthreads();

        const __nv_bfloat16* Ash = sm + (kt & 1) * BUFSZ;
        const __nv_bfloat16* Asl = Ash + ATILE;
        const __nv_bfloat16* Bsh = Asl + ATILE;
        const __nv_bfloat16* Bsl = Bsh + ATILE;

        #pragma unroll
        for (int kk = 0; kk < 2; kk++) {
            int ks = kk * 16;
            uint32_t ah[2][4], alo_[2][4];
            #pragma unroll
            for (int mt = 0; mt < 2; mt++) {
                int r0 = (wm * 32 + mt * 16 + g) * SA;
                int r1 = r0 + 8 * SA;
                ah[mt][0] = *(const uint32_t*)&Ash[r0 + ks + 2 * t];
                ah[mt][1] = *(const uint32_t*)&Ash[r1 + ks + 2 * t];
                ah[mt][2] = *(const uint32_t*)&Ash[r0 + ks + 2 * t + 8];
                ah[mt][3] = *(const uint32_t*)&Ash[r1 + ks + 2 * t + 8];
                alo_[mt][0] = *(const uint32_t*)&Asl[r0 + ks + 2 * t];
                alo_[mt][1] = *(const uint32_t*)&Asl[r1 + ks + 2 * t];
                alo_[mt][2] = *(const uint32_t*)&Asl[r0 + ks + 2 * t + 8];
                alo_[mt][3] = *(const uint32_t*)&Asl[r1 + ks + 2 * t + 8];
            }
            #pragma unroll
            for (int nt = 0; nt < 8; nt++) {
                int nb = (wn * 64 + nt * 8 + g) * SA;
                uint32_t bh0 = *(const uint32_t*)&Bsh[nb + ks + 2 * t];
                uint32_t bh1 = *(const uint32_t*)&Bsh[nb + ks + 2 * t + 8];
                uint32_t bl0 = *(const uint32_t*)&Bsl[nb + ks + 2 * t];
                uint32_t bl1 = *(const uint32_t*)&Bsl[nb + ks + 2 * t + 8];
                #pragma unroll
                for (int mt = 0; mt < 2; mt++) {
                    mma_bf16(acc[mt][nt], ah[mt], bh0, bh1);
                    mma_bf16(acc[mt][nt], ah[mt], bl0, bl1);
                    mma_bf16(acc[mt][nt], alo_[mt], bh0, bh1);
                }
            }
        }
        __syncthreads();
    }

    // ---- epilogue: write h fp16 + fused el/er ----
    int head = blockIdx.y * 2 + wn;               // this warp's head
    float2 alv[8], arv[8];
    #pragma unroll
    for (int nt = 0; nt < 8; nt++) {
        int d = nt * 8 + 2 * t;                   // 0..63 within head
        alv[nt] = *(const float2*)(al + head * 64 + d);
        arv[nt] = *(const float2*)(ar + head * 64 + d);
    }

    #pragma unroll
    for (int mt = 0; mt < 2; mt++) {
        int r0 = rowBase + wm * 32 + mt * 16 + g;
        int r1 = r0 + 8;
        float el0 = 0.f, er0 = 0.f, el1 = 0.f, er1 = 0.f;
        #pragma unroll
        for (int nt = 0; nt < 8; nt++) {
            int col = nbase + wn * 64 + nt * 8 + 2 * t;
            if (r0 < nrows)
                *(__half2*)(g_hh + (size_t)r0 * 256 + col) =
                    __floats2half2_rn(acc[mt][nt][0], acc[mt][nt][1]);
            if (r1 < nrows)
                *(__half2*)(g_hh + (size_t)r1 * 256 + col) =
                    __floats2half2_rn(acc[mt][nt][2], acc[mt][nt][3]);
            el0 += acc[mt][nt][0] * alv[nt].x + acc[mt][nt][1] * alv[nt].y;
            er0 += acc[mt][nt][0] * arv[nt].x + acc[mt][nt][1] * arv[nt].y;
            el1 += acc[mt][nt][2] * alv[nt].x + acc[mt][nt][3] * alv[nt].y;
            er1 += acc[mt][nt][2] * arv[nt].x + acc[mt][nt][3] * arv[nt].y;
        }
        // reduce over the 4 t-lanes (consecutive lanes 4g..4g+3)
        #pragma unroll
        for (int o = 1; o < 4; o <<= 1) {
            el0 += __shfl_xor_sync(0xffffffffu, el0, o);
            er0 += __shfl_xor_sync(0xffffffffu, er0, o);
            el1 += __shfl_xor_sync(0xffffffffu, el1, o);
            er1 += __shfl_xor_sync(0xffffffffu, er1, o);
        }
        if (t == 0) {
            if (r0 < nrows) { g_el[r0 * 4 + head] = el0; g_er[r0 * 4 + head] = er0; }
            if (r1 < nrows) { g_el[r1 * 4 + head] = el1; g_er[r1 * 4 + head] = er1; }
        }
    }
}

// ---------- fused edge-softmax + aggregation (fp16 gather, 128 thr/node) -----
// tid covers features 2*tid, 2*tid+1; head = tid>>5.
__global__ __launch_bounds__(128) void aggregate_kernel(
    const int* __restrict__ src, const float* __restrict__ bias,
    float* __restrict__ outf, int write_bf16)
{
    int n = blockIdx.x;
    int tid = threadIdx.x;
    int hh = tid >> 5;
    int beg = g_off[n], end = g_off[n + 1];

    __shared__ int   s_src[128];
    __shared__ float s_a[128 * 4];

    float4 rn = ((const float4*)g_er)[n];
    float acc0 = 0.f, acc1 = 0.f, den = 0.f;
    const __half2* htab = (const __half2*)g_hh;

    for (int base = beg; base < end; base += 128) {
        int cnt = min(128, end - base);
        __syncthreads();
        for (int i = tid; i < cnt; i += 128) {
            int eid = g_eidx[base + i];
            int s = src[eid];
            s_src[i] = s;
            float4 l = ((const float4*)g_el)[s];
            float4 w;
            float e0 = l.x + rn.x; e0 = (e0 > 0.f) ? e0 : 0.2f * e0; w.x = __expf(e0);
            float e1 = l.y + rn.y; e1 = (e1 > 0.f) ? e1 : 0.2f * e1; w.y = __expf(e1);
            float e2 = l.z + rn.z; e2 = (e2 > 0.f) ? e2 : 0.2f * e2; w.z = __expf(e2);
            float e3 = l.w + rn.w; e3 = (e3 > 0.f) ? e3 : 0.2f * e3; w.w = __expf(e3);
            ((float4*)s_a)[i] = w;
        }
        __syncthreads();
        int i = 0;
        for (; i + 4 <= cnt; i += 4) {
            float a0 = s_a[(i + 0) * 4 + hh];
            float a1 = s_a[(i + 1) * 4 + hh];
            float a2 = s_a[(i + 2) * 4 + hh];
            float a3 = s_a[(i + 3) * 4 + hh];
            int s0 = s_src[i], s1 = s_src[i + 1], s2 = s_src[i + 2], s3 = s_src[i + 3];
            float2 h0 = __half22float2(htab[(size_t)s0 * 128 + tid]);
            float2 h1 = __half22float2(htab[(size_t)s1 * 128 + tid]);
            float2 h2 = __half22float2(htab[(size_t)s2 * 128 + tid]);
            float2 h3 = __half22float2(htab[(size_t)s3 * 128 + tid]);
            acc0 += a0 * h0.x + a1 * h1.x + a2 * h2.x + a3 * h3.x;
            acc1 += a0 * h0.y + a1 * h1.y + a2 * h2.y + a3 * h3.y;
            den += (a0 + a1) + (a2 + a3);
        }
        for (; i < cnt; i++) {
            float a = s_a[i * 4 + hh];
            float2 hv = __half22float2(htab[(size_t)s_src[i] * 128 + tid]);
            acc0 += a * hv.x;
            acc1 += a * hv.y;
            den += a;
        }
    }
    float inv = 1.f / den;
    float v0 = fmaxf(acc0 * inv + bias[2 * tid], 0.f);
    float v1 = fmaxf(acc1 * inv + bias[2 * tid + 1], 0.f);
    size_t oi = (size_t)n * 256 + 2 * tid;
    if (write_bf16) {
        __nv_bfloat16 h0 = __float2bfloat16_rn(v0);
        __nv_bfloat16 h1 = __float2bfloat16_rn(v1);
        g_Ahi[oi] = h0;
        g_Ahi[oi + 1] = h1;
        g_Alo[oi] = __float2bfloat16_rn(v0 - __bfloat162float(h0));
        g_Alo[oi + 1] = __float2bfloat16_rn(v1 - __bfloat162float(h1));
    } else {
        *(float2*)(outf + oi) = make_float2(v0, v1);
    }
}

// ---------------- launch ----------------
extern "C" void kernel_launch(void* const* d_in, const int* in_sizes, int n_in,
                              void* d_out, int out_size)
{
    const float* feat = (const float*)d_in[0];
    const int*   src  = (const int*)d_in[1];
    const int*   dst  = (const int*)d_in[2];
    const float* W1   = (const float*)d_in[3];
    const float* al1  = (const float*)d_in[4];
    const float* ar1  = (const float*)d_in[5];
    const float* b1   = (const float*)d_in[6];
    const float* W2   = (const float*)d_in[7];
    const float* al2  = (const float*)d_in[8];
    const float* ar2  = (const float*)d_in[9];
    const float* b2   = (const float*)d_in[10];
    float* out = (float*)d_out;
    int E = in_sizes[1];

    void* p;
    cudaGetSymbolAddress(&p, g_Ahi); __nv_bfloat16* ahi = (__nv_bfloat16*)p;
    cudaGetSymbolAddress(&p, g_Alo); __nv_bfloat16* alo = (__nv_bfloat16*)p;

    static int smem_set = 0;
    if (!smem_set) {
        cudaFuncSetAttribute(gemm_mma_kernel,
                             cudaFuncAttributeMaxDynamicSharedMemorySize, GEMM_SMEM);
        smem_set = 1;
    }

    int egrid = (E + 255) / 256;
    int ngrid = (NN + 255) / 256;
    dim3 ggrid((NN + 127) / 128, 2);

    // CSR build (same for both layers)
    zero_indeg_kernel<<<ngrid, 256>>>();
    csr_count_kernel<<<egrid, 256>>>(dst, E);
    scan_kernel<<<1, 1024>>>();
    csr_scatter_kernel<<<egrid, 256>>>(dst, E);

    // layer 1
    asplit_kernel<<<NN, 256>>>(feat);
    wsplit_kernel<<<256, 256>>>(W1);
    gemm_mma_kernel<<<ggrid, 256, GEMM_SMEM>>>(ahi, alo, al1, ar1, NN);
    aggregate_kernel<<<NN, 128>>>(src, b1, nullptr, 1);

    // layer 2
    wsplit_kernel<<<256, 256>>>(W2);
    gemm_mma_kernel<<<ggrid, 256, GEMM_SMEM>>>(ahi, alo, al2, ar2, NN);
    aggregate_kernel<<<NN, 128>>>(src, b2, out, 0);
}

// round 6
// speedup vs baseline: 1.5317x; 1.0145x over previous
#include <cuda_runtime.h>
#include <cuda_bf16.h>
#include <cuda_fp16.h>
#include <cstdint>
#include <cstddef>

#define NN 50000
#define EE 850000
#define HH 4

// ---------------- scratch (static device globals; no runtime alloc) ----------
__device__ __half g_hh[(size_t)NN * 256];     // h in fp16 (gather table)
__device__ float g_el[NN * HH];
__device__ float g_er[NN * HH];
__device__ int   g_indeg[NN];
__device__ int   g_off[NN + 1];
__device__ int   g_cur[NN];
__device__ int   g_csrc[EE];                  // CSR payload: src node id
__device__ __nv_bfloat16 g_Ahi[(size_t)NN * 256];
__device__ __nv_bfloat16 g_Alo[(size_t)NN * 256];
__device__ __nv_bfloat16 g_Wthi[256 * 256];   // W split-hi, transposed [n][k]
__device__ __nv_bfloat16 g_Wtlo[256 * 256];   // W split-lo, transposed [n][k]

// ---------------- PTX helpers ----------------
__device__ __forceinline__ uint32_t smem_u32(const void* p) {
    uint32_t a;
    asm("{ .reg .u64 t; cvta.to.shared.u64 t, %1; cvt.u32.u64 %0, t; }"
        : "=r"(a) : "l"(p));
    return a;
}
#define CP_ASYNC16(dst, src) \
    asm volatile("cp.async.cg.shared.global [%0], [%1], 16;" :: "r"(dst), "l"(src))
#define CP_COMMIT() asm volatile("cp.async.commit_group;" ::: "memory")
#define CP_WAIT(n)  asm volatile("cp.async.wait_group %0;" :: "n"(n) : "memory")

__device__ __forceinline__ void mma_bf16(float* c, const uint32_t* a,
                                         uint32_t b0, uint32_t b1) {
    asm volatile(
        "mma.sync.aligned.m16n8k16.row.col.f32.bf16.bf16.f32 "
        "{%0,%1,%2,%3}, {%4,%5,%6,%7}, {%8,%9}, {%0,%1,%2,%3};"
        : "+f"(c[0]), "+f"(c[1]), "+f"(c[2]), "+f"(c[3])
        : "r"(a[0]), "r"(a[1]), "r"(a[2]), "r"(a[3]), "r"(b0), "r"(b1));
}
__device__ __forceinline__ void ldm_x4(uint32_t* r, uint32_t addr) {
    asm volatile(
        "ldmatrix.sync.aligned.m8n8.x4.shared.b16 {%0,%1,%2,%3}, [%4];"
        : "=r"(r[0]), "=r"(r[1]), "=r"(r[2]), "=r"(r[3]) : "r"(addr));
}

// ---------------- CSR build ----------------
__global__ void zero_indeg_kernel() {
    int i = blockIdx.x * blockDim.x + threadIdx.x;
    if (i < NN) g_indeg[i] = 0;
}

__global__ void csr_count_kernel(const int* __restrict__ dst, int E) {
    int e = blockIdx.x * blockDim.x + threadIdx.x;
    if (e < E) atomicAdd(&g_indeg[dst[e]], 1);
}

__global__ void scan_kernel() {
    __shared__ int warp_sums[32];
    __shared__ int s_carry;
    int tid = threadIdx.x;
    int lane = tid & 31, wid = tid >> 5;
    if (tid == 0) s_carry = 0;
    __syncthreads();
    for (int base = 0; base < NN; base += 1024) {
        int idx = base + tid;
        int v = (idx < NN) ? g_indeg[idx] : 0;
        int x = v;
        #pragma unroll
        for (int o = 1; o < 32; o <<= 1) {
            int t = __shfl_up_sync(0xffffffffu, x, o);
            if (lane >= o) x += t;
        }
        if (lane == 31) warp_sums[wid] = x;
        __syncthreads();
        if (wid == 0) {
            int ws = warp_sums[lane];
            #pragma unroll
            for (int o = 1; o < 32; o <<= 1) {
                int t = __shfl_up_sync(0xffffffffu, ws, o);
                if (lane >= o) ws += t;
            }
            warp_sums[lane] = ws;
        }
        __syncthreads();
        int warp_excl = (wid == 0) ? 0 : warp_sums[wid - 1];
        int excl = x - v + warp_excl + s_carry;
        if (idx < NN) { g_off[idx] = excl; g_cur[idx] = excl; }
        __syncthreads();
        if (tid == 0) s_carry += warp_sums[31];
        __syncthreads();
    }
    if (threadIdx.x == 0) g_off[NN] = s_carry;
}

__global__ void csr_scatter_kernel(const int* __restrict__ dst,
                                   const int* __restrict__ src, int E) {
    int e = blockIdx.x * blockDim.x + threadIdx.x;
    if (e < E) {
        int p = atomicAdd(&g_cur[dst[e]], 1);
        g_csrc[p] = src[e];
    }
}

// ---------------- splits ----------------
__global__ void wsplit_kernel(const float* __restrict__ W) {
    int idx = blockIdx.x * 256 + threadIdx.x;
    int k = idx >> 8, n = idx & 255;
    float v = W[k * 256 + n];
    __nv_bfloat16 hi = __float2bfloat16_rn(v);
    __nv_bfloat16 lo = __float2bfloat16_rn(v - __bfloat162float(hi));
    g_Wthi[n * 256 + k] = hi;
    g_Wtlo[n * 256 + k] = lo;
}

__global__ void asplit_kernel(const float* __restrict__ X) {
    size_t i = (size_t)blockIdx.x * 256 + threadIdx.x;
    float v = X[i];
    __nv_bfloat16 hi = __float2bfloat16_rn(v);
    __nv_bfloat16 lo = __float2bfloat16_rn(v - __bfloat162float(hi));
    g_Ahi[i] = hi;
    g_Alo[i] = lo;
}

// --------- bf16x3 mma.sync GEMM (ldmatrix fragments) + fused attn epilogue ---
#define SA 40
#define ATILE (128 * SA)
#define BUFSZ (4 * ATILE)
#define GEMM_SMEM (2 * BUFSZ * 2)

__global__ __launch_bounds__(256) void gemm_mma_kernel(
    const __nv_bfloat16* __restrict__ Ahi, const __nv_bfloat16* __restrict__ Alo,
    const float* __restrict__ al, const float* __restrict__ ar, int nrows)
{
    extern __shared__ __nv_bfloat16 sm[];
    int tid = threadIdx.x;
    int lane = tid & 31;
    int wid = tid >> 5;
    int wm = wid & 3, wn = wid >> 2;
    int g = lane >> 2, t = lane & 3;
    int rowBase = blockIdx.x * 128;
    int nbase = blockIdx.y * 128;

    uint32_t sb = smem_u32(sm);

    // ldmatrix per-lane address offsets (bytes within one buffer)
    uint32_t aOff = (uint32_t)(((wm * 32 + (lane & 15)) * SA + ((lane >> 4) << 3)) * 2);
    uint32_t bOff = (uint32_t)(((wn * 64 + ((lane >> 4) << 3) + (lane & 7)) * SA +
                                (((lane >> 3) & 1) << 3)) * 2);

    float acc[2][8][4];
    #pragma unroll
    for (int mt = 0; mt < 2; mt++)
        #pragma unroll
        for (int nt = 0; nt < 8; nt++)
            #pragma unroll
            for (int q = 0; q < 4; q++) acc[mt][nt][q] = 0.f;

    #define STAGE(buf, k0)                                                        \
    do {                                                                          \
        uint32_t base = sb + (uint32_t)(buf) * (BUFSZ * 2);                       \
        _Pragma("unroll")                                                         \
        for (int p = 0; p < 2; p++) {                                             \
            int c = tid + p * 256;                                                \
            int r = c >> 2, j = c & 3;                                            \
            uint32_t so = (uint32_t)(r * (SA * 2) + j * 16);                      \
            int arow = rowBase + r;                                               \
            if (arow < nrows) {                                                   \
                const __nv_bfloat16* ga = Ahi + (size_t)arow * 256 + (k0) + j * 8;\
                const __nv_bfloat16* gb = Alo + (size_t)arow * 256 + (k0) + j * 8;\
                CP_ASYNC16(base + so, ga);                                        \
                CP_ASYNC16(base + ATILE * 2 + so, gb);                            \
            }                                                                     \
            const __nv_bfloat16* gh = g_Wthi + (size_t)(nbase + r) * 256 + (k0) + j * 8; \
            const __nv_bfloat16* gl = g_Wtlo + (size_t)(nbase + r) * 256 + (k0) + j * 8; \
            CP_ASYNC16(base + ATILE * 4 + so, gh);                                \
            CP_ASYNC16(base + ATILE * 6 + so, gl);                                \
        }                                                                         \
        CP_COMMIT();                                                              \
    } while (0)

    STAGE(0, 0);

    #pragma unroll
    for (int kt = 0; kt < 8; kt++) {
        if (kt < 7) STAGE((kt + 1) & 1, (kt + 1) * 32);
        if (kt < 7) { CP_WAIT(1); } else { CP_WAIT(0); }
        __syncthreads();

        uint32_t bufb = sb + (uint32_t)(kt & 1) * (BUFSZ * 2);
        uint32_t aH = bufb + aOff;
        uint32_t aL = aH + ATILE * 2;
        uint32_t bH = bufb + ATILE * 4 + bOff;
        uint32_t bL = bH + ATILE * 2;

        #pragma unroll
        for (int kk = 0; kk < 2; kk++) {
            uint32_t ksb = (uint32_t)(kk * 32);   // 16 halves = 32 bytes
            uint32_t ah[2][4], alo_[2][4];
            #pragma unroll
            for (int mt = 0; mt < 2; mt++) {
                ldm_x4(ah[mt], aH + (uint32_t)(mt * 16 * SA * 2) + ksb);
                ldm_x4(alo_[mt], aL + (uint32_t)(mt * 16 * SA * 2) + ksb);
            }
            #pragma unroll
            for (int p = 0; p < 4; p++) {
                uint32_t bh[4], bl[4];
                ldm_x4(bh, bH + (uint32_t)(p * 16 * SA * 2) + ksb);
                ldm_x4(bl, bL + (uint32_t)(p * 16 * SA * 2) + ksb);
                #pragma unroll
                for (int sub = 0; sub < 2; sub++) {
                    int nt = p * 2 + sub;
                    #pragma unroll
                    for (int mt = 0; mt < 2; mt++) {
                        mma_bf16(acc[mt][nt], ah[mt], bh[2 * sub], bh[2 * sub + 1]);
                        mma_bf16(acc[mt][nt], ah[mt], bl[2 * sub], bl[2 * sub + 1]);
                        mma_bf16(acc[mt][nt], alo_[mt], bh[2 * sub], bh[2 * sub + 1]);
                    }
                }
            }
        }
        __syncthreads();
    }

    // ---- epilogue: write h fp16 + fused el/er ----
    int head = blockIdx.y * 2 + wn;
    float2 alv[8], arv[8];
    #pragma unroll
    for (int nt = 0; nt < 8; nt++) {
        int d = nt * 8 + 2 * t;
        alv[nt] = *(const float2*)(al + head * 64 + d);
        arv[nt] = *(const float2*)(ar + head * 64 + d);
    }

    #pragma unroll
    for (int mt = 0; mt < 2; mt++) {
        int r0 = rowBase + wm * 32 + mt * 16 + g;
        int r1 = r0 + 8;
        float el0 = 0.f, er0 = 0.f, el1 = 0.f, er1 = 0.f;
        #pragma unroll
        for (int nt = 0; nt < 8; nt++) {
            int col = nbase + wn * 64 + nt * 8 + 2 * t;
            if (r0 < nrows)
                *(__half2*)(g_hh + (size_t)r0 * 256 + col) =
                    __floats2half2_rn(acc[mt][nt][0], acc[mt][nt][1]);
            if (r1 < nrows)
                *(__half2*)(g_hh + (size_t)r1 * 256 + col) =
                    __floats2half2_rn(acc[mt][nt][2], acc[mt][nt][3]);
            el0 += acc[mt][nt][0] * alv[nt].x + acc[mt][nt][1] * alv[nt].y;
            er0 += acc[mt][nt][0] * arv[nt].x + acc[mt][nt][1] * arv[nt].y;
            el1 += acc[mt][nt][2] * alv[nt].x + acc[mt][nt][3] * alv[nt].y;
            er1 += acc[mt][nt][2] * arv[nt].x + acc[mt][nt][3] * arv[nt].y;
        }
        #pragma unroll
        for (int o = 1; o < 4; o <<= 1) {
            el0 += __shfl_xor_sync(0xffffffffu, el0, o);
            er0 += __shfl_xor_sync(0xffffffffu, er0, o);
            el1 += __shfl_xor_sync(0xffffffffu, el1, o);
            er1 += __shfl_xor_sync(0xffffffffu, er1, o);
        }
        if (t == 0) {
            if (r0 < nrows) { g_el[r0 * 4 + head] = el0; g_er[r0 * 4 + head] = er0; }
            if (r1 < nrows) { g_el[r1 * 4 + head] = el1; g_er[r1 * 4 + head] = er1; }
        }
    }
}

// ---------- fused edge-softmax + aggregation (fp16 gather, 128 thr/node) -----
__global__ __launch_bounds__(128) void aggregate_kernel(
    const float* __restrict__ bias, float* __restrict__ outf, int write_bf16)
{
    int n = blockIdx.x;
    int tid = threadIdx.x;
    int hh = tid >> 5;
    int beg = g_off[n], end = g_off[n + 1];

    __shared__ int   s_src[128];
    __shared__ float s_a[128 * 4];

    float4 rn = ((const float4*)g_er)[n];
    float acc0 = 0.f, acc1 = 0.f, den = 0.f;
    const __half2* htab = (const __half2*)g_hh;

    for (int base = beg; base < end; base += 128) {
        int cnt = min(128, end - base);
        __syncthreads();
        for (int i = tid; i < cnt; i += 128) {
            int s = g_csrc[base + i];
            s_src[i] = s;
            float4 l = ((const float4*)g_el)[s];
            float4 w;
            float e0 = l.x + rn.x; e0 = (e0 > 0.f) ? e0 : 0.2f * e0; w.x = __expf(e0);
            float e1 = l.y + rn.y; e1 = (e1 > 0.f) ? e1 : 0.2f * e1; w.y = __expf(e1);
            float e2 = l.z + rn.z; e2 = (e2 > 0.f) ? e2 : 0.2f * e2; w.z = __expf(e2);
            float e3 = l.w + rn.w; e3 = (e3 > 0.f) ? e3 : 0.2f * e3; w.w = __expf(e3);
            ((float4*)s_a)[i] = w;
        }
        __syncthreads();
        int i = 0;
        for (; i + 4 <= cnt; i += 4) {
            float a0 = s_a[(i + 0) * 4 + hh];
            float a1 = s_a[(i + 1) * 4 + hh];
            float a2 = s_a[(i + 2) * 4 + hh];
            float a3 = s_a[(i + 3) * 4 + hh];
            int s0 = s_src[i], s1 = s_src[i + 1], s2 = s_src[i + 2], s3 = s_src[i + 3];
            float2 h0 = __half22float2(htab[(size_t)s0 * 128 + tid]);
            float2 h1 = __half22float2(htab[(size_t)s1 * 128 + tid]);
            float2 h2 = __half22float2(htab[(size_t)s2 * 128 + tid]);
            float2 h3 = __half22float2(htab[(size_t)s3 * 128 + tid]);
            acc0 += a0 * h0.x + a1 * h1.x + a2 * h2.x + a3 * h3.x;
            acc1 += a0 * h0.y + a1 * h1.y + a2 * h2.y + a3 * h3.y;
            den += (a0 + a1) + (a2 + a3);
        }
        for (; i < cnt; i++) {
            float a = s_a[i * 4 + hh];
            float2 hv = __half22float2(htab[(size_t)s_src[i] * 128 + tid]);
            acc0 += a * hv.x;
            acc1 += a * hv.y;
            den += a;
        }
    }
    float inv = 1.f / den;
    float v0 = fmaxf(acc0 * inv + bias[2 * tid], 0.f);
    float v1 = fmaxf(acc1 * inv + bias[2 * tid + 1], 0.f);
    size_t oi = (size_t)n * 256 + 2 * tid;
    if (write_bf16) {
        __nv_bfloat16 h0 = __float2bfloat16_rn(v0);
        __nv_bfloat16 h1 = __float2bfloat16_rn(v1);
        g_Ahi[oi] = h0;
        g_Ahi[oi + 1] = h1;
        g_Alo[oi] = __float2bfloat16_rn(v0 - __bfloat162float(h0));
        g_Alo[oi + 1] = __float2bfloat16_rn(v1 - __bfloat162float(h1));
    } else {
        *(float2*)(outf + oi) = make_float2(v0, v1);
    }
}

// ---------------- launch ----------------
extern "C" void kernel_launch(void* const* d_in, const int* in_sizes, int n_in,
                              void* d_out, int out_size)
{
    const float* feat = (const float*)d_in[0];
    const int*   src  = (const int*)d_in[1];
    const int*   dst  = (const int*)d_in[2];
    const float* W1   = (const float*)d_in[3];
    const float* al1  = (const float*)d_in[4];
    const float* ar1  = (const float*)d_in[5];
    const float* b1   = (const float*)d_in[6];
    const float* W2   = (const float*)d_in[7];
    const float* al2  = (const float*)d_in[8];
    const float* ar2  = (const float*)d_in[9];
    const float* b2   = (const float*)d_in[10];
    float* out = (float*)d_out;
    int E = in_sizes[1];

    void* p;
    cudaGetSymbolAddress(&p, g_Ahi); __nv_bfloat16* ahi = (__nv_bfloat16*)p;
    cudaGetSymbolAddress(&p, g_Alo); __nv_bfloat16* alo = (__nv_bfloat16*)p;

    static int smem_set = 0;
    if (!smem_set) {
        cudaFuncSetAttribute(gemm_mma_kernel,
                             cudaFuncAttributeMaxDynamicSharedMemorySize, GEMM_SMEM);
        smem_set = 1;
    }

    int egrid = (E + 255) / 256;
    int ngrid = (NN + 255) / 256;
    dim3 ggrid((NN + 127) / 128, 2);

    // CSR build (same for both layers)
    zero_indeg_kernel<<<ngrid, 256>>>();
    csr_count_kernel<<<egrid, 256>>>(dst, E);
    scan_kernel<<<1, 1024>>>();
    csr_scatter_kernel<<<egrid, 256>>>(dst, src, E);

    // layer 1
    asplit_kernel<<<NN, 256>>>(feat);
    wsplit_kernel<<<256, 256>>>(W1);
    gemm_mma_kernel<<<ggrid, 256, GEMM_SMEM>>>(ahi, alo, al1, ar1, NN);
    aggregate_kernel<<<NN, 128>>>(b1, nullptr, 1);

    // layer 2
    wsplit_kernel<<<256, 256>>>(W2);
    gemm_mma_kernel<<<ggrid, 256, GEMM_SMEM>>>(ahi, alo, al2, ar2, NN);
    aggregate_kernel<<<NN, 128>>>(b2, out, 0);
}

// round 8
// speedup vs baseline: 1.9941x; 1.3019x over previous
#include <cuda_runtime.h>
#include <cuda_fp16.h>
#include <cstdint>
#include <cstddef>

#define NN 50000
#define EE 850000
#define HH 4

// ---------------- scratch (static device globals; no runtime alloc) ----------
__device__ __half g_hh[(size_t)NN * 256];     // h in fp16 (gather table)
__device__ float g_el[NN * HH];
__device__ float g_er[NN * HH];
__device__ __align__(16) int g_indeg[NN];
__device__ __align__(16) int g_off[NN + 4];
__device__ __align__(16) int g_cur[NN];
__device__ int   g_csrc[EE];                  // CSR payload: src node id
__device__ __half g_Ah[(size_t)NN * 256];     // GEMM input (fp16)
__device__ __half g_Wthi[256 * 256];          // W split-hi, transposed [n][k]
__device__ __half g_Wtlo[256 * 256];          // W split-lo, transposed [n][k]

// ---------------- PTX helpers ----------------
__device__ __forceinline__ uint32_t smem_u32(const void* p) {
    uint32_t a;
    asm("{ .reg .u64 t; cvta.to.shared.u64 t, %1; cvt.u32.u64 %0, t; }"
        : "=r"(a) : "l"(p));
    return a;
}
#define CP_ASYNC16(dst, src) \
    asm volatile("cp.async.cg.shared.global [%0], [%1], 16;" :: "r"(dst), "l"(src))
#define CP_COMMIT() asm volatile("cp.async.commit_group;" ::: "memory")
#define CP_WAIT(n)  asm volatile("cp.async.wait_group %0;" :: "n"(n) : "memory")

__device__ __forceinline__ void mma_f16(float* c, const uint32_t* a,
                                        uint32_t b0, uint32_t b1) {
    asm volatile(
        "mma.sync.aligned.m16n8k16.row.col.f32.f16.f16.f32 "
        "{%0,%1,%2,%3}, {%4,%5,%6,%7}, {%8,%9}, {%0,%1,%2,%3};"
        : "+f"(c[0]), "+f"(c[1]), "+f"(c[2]), "+f"(c[3])
        : "r"(a[0]), "r"(a[1]), "r"(a[2]), "r"(a[3]), "r"(b0), "r"(b1));
}
__device__ __forceinline__ void ldm_x4(uint32_t* r, uint32_t addr) {
    asm volatile(
        "ldmatrix.sync.aligned.m8n8.x4.shared.b16 {%0,%1,%2,%3}, [%4];"
        : "=r"(r[0]), "=r"(r[1]), "=r"(r[2]), "=r"(r[3]) : "r"(addr));
}

// ---------------- CSR build ----------------
__global__ void zero_indeg_kernel() {
    int i = blockIdx.x * blockDim.x + threadIdx.x;
    if (i < NN) g_indeg[i] = 0;
}

__global__ void csr_count_kernel(const int* __restrict__ dst, int E) {
    int e = blockIdx.x * blockDim.x + threadIdx.x;
    if (e < E) atomicAdd(&g_indeg[dst[e]], 1);
}

__global__ void scan_kernel() {
    __shared__ int warp_sums[32];
    __shared__ int s_carry;
    int tid = threadIdx.x;
    int lane = tid & 31, wid = tid >> 5;
    if (tid == 0) s_carry = 0;
    __syncthreads();
    const int NQ = NN / 4;                     // 12500 int4 groups
    for (int base = 0; base < NQ; base += 1024) {
        int idx = base + tid;
        int4 v = make_int4(0, 0, 0, 0);
        if (idx < NQ) v = ((const int4*)g_indeg)[idx];
        int tot = v.x + v.y + v.z + v.w;
        int x = tot;
        #pragma unroll
        for (int o = 1; o < 32; o <<= 1) {
            int t = __shfl_up_sync(0xffffffffu, x, o);
            if (lane >= o) x += t;
        }
        if (lane == 31) warp_sums[wid] = x;
        __syncthreads();
        if (wid == 0) {
            int ws = warp_sums[lane];
            #pragma unroll
            for (int o = 1; o < 32; o <<= 1) {
                int t = __shfl_up_sync(0xffffffffu, ws, o);
                if (lane >= o) ws += t;
            }
            warp_sums[lane] = ws;
        }
        __syncthreads();
        int warp_excl = (wid == 0) ? 0 : warp_sums[wid - 1];
        int excl = x - tot + warp_excl + s_carry;
        if (idx < NQ) {
            int4 o;
            o.x = excl;
            o.y = o.x + v.x;
            o.z = o.y + v.y;
            o.w = o.z + v.z;
            ((int4*)g_off)[idx] = o;
            ((int4*)g_cur)[idx] = o;
        }
        __syncthreads();
        if (tid == 0) s_carry += warp_sums[31];
        __syncthreads();
    }
    if (threadIdx.x == 0) g_off[NN] = s_carry;
}

__global__ void csr_scatter_kernel(const int* __restrict__ dst,
                                   const int* __restrict__ src, int E) {
    int e = blockIdx.x * blockDim.x + threadIdx.x;
    if (e < E) {
        int p = atomicAdd(&g_cur[dst[e]], 1);
        g_csrc[p] = src[e];
    }
}

// ---------------- splits ----------------
__global__ void wsplit_kernel(const float* __restrict__ W) {
    int idx = blockIdx.x * 256 + threadIdx.x;
    int k = idx >> 8, n = idx & 255;
    float v = W[k * 256 + n];
    __half hi = __float2half_rn(v);
    __half lo = __float2half_rn(v - __half2float(hi));
    g_Wthi[n * 256 + k] = hi;
    g_Wtlo[n * 256 + k] = lo;
}

__global__ void asplit_kernel(const float* __restrict__ X) {
    size_t i = ((size_t)blockIdx.x * 256 + threadIdx.x) * 2;
    float2 v = *(const float2*)(X + i);
    *(__half2*)(g_Ah + i) = __floats2half2_rn(v.x, v.y);
}

// --------- fp16x2 mma.sync GEMM (A fp16, W hi+lo) + fused attn epilogue ------
// C = A·Wh + A·Wl ; BM=128, BN=128, BK=32; 256 thr = 8 warps (4m x 2n).
#define SA 40
#define ATILE (128 * SA)                 // halves per array (5120) = 10240 B
#define BUFB (3 * ATILE * 2)             // bytes per buffer: A, Bh, Bl = 30720
#define GEMM_SMEM (2 * BUFB)             // 61440 B

__global__ __launch_bounds__(256) void gemm_mma_kernel(
    const __half* __restrict__ A,
    const float* __restrict__ al, const float* __restrict__ ar, int nrows)
{
    extern __shared__ __half sm[];
    int tid = threadIdx.x;
    int lane = tid & 31;
    int wid = tid >> 5;
    int wm = wid & 3, wn = wid >> 2;
    int g = lane >> 2, t = lane & 3;
    int rowBase = blockIdx.x * 128;
    int nbase = blockIdx.y * 128;

    uint32_t sb = smem_u32(sm);

    uint32_t aOff = (uint32_t)(((wm * 32 + (lane & 15)) * SA + ((lane >> 4) << 3)) * 2);
    uint32_t bOff = (uint32_t)(((wn * 64 + ((lane >> 4) << 3) + (lane & 7)) * SA +
                                (((lane >> 3) & 1) << 3)) * 2);

    float acc[2][8][4];
    #pragma unroll
    for (int mt = 0; mt < 2; mt++)
        #pragma unroll
        for (int nt = 0; nt < 8; nt++)
            #pragma unroll
            for (int q = 0; q < 4; q++) acc[mt][nt][q] = 0.f;

    #define STAGE(buf, k0)                                                        \
    do {                                                                          \
        uint32_t base = sb + (uint32_t)(buf) * BUFB;                              \
        _Pragma("unroll")                                                         \
        for (int p = 0; p < 2; p++) {                                             \
            int c = tid + p * 256;                                                \
            int r = c >> 2, j = c & 3;                                            \
            uint32_t so = (uint32_t)(r * (SA * 2) + j * 16);                      \
            int arow = rowBase + r;                                               \
            if (arow < nrows)                                                     \
                CP_ASYNC16(base + so, A + (size_t)arow * 256 + (k0) + j * 8);     \
            CP_ASYNC16(base + ATILE * 2 + so,                                     \
                       g_Wthi + (size_t)(nbase + r) * 256 + (k0) + j * 8);        \
            CP_ASYNC16(base + ATILE * 4 + so,                                     \
                       g_Wtlo + (size_t)(nbase + r) * 256 + (k0) + j * 8);        \
        }                                                                         \
        CP_COMMIT();                                                              \
    } while (0)

    STAGE(0, 0);

    #pragma unroll
    for (int kt = 0; kt < 8; kt++) {
        if (kt < 7) STAGE((kt + 1) & 1, (kt + 1) * 32);
        if (kt < 7) { CP_WAIT(1); } else { CP_WAIT(0); }
        __syncthreads();

        uint32_t bufb = sb + (uint32_t)(kt & 1) * BUFB;
        uint32_t aP = bufb + aOff;
        uint32_t bH = bufb + ATILE * 2 + bOff;
        uint32_t bL = bufb + ATILE * 4 + bOff;

        #pragma unroll
        for (int kk = 0; kk < 2; kk++) {
            uint32_t ksb = (uint32_t)(kk * 32);
            uint32_t ah[2][4];
            #pragma unroll
            for (int mt = 0; mt < 2; mt++)
                ldm_x4(ah[mt], aP + (uint32_t)(mt * 16 * SA * 2) + ksb);
            #pragma unroll
            for (int p = 0; p < 4; p++) {
                uint32_t bh[4], bl[4];
                ldm_x4(bh, bH + (uint32_t)(p * 16 * SA * 2) + ksb);
                ldm_x4(bl, bL + (uint32_t)(p * 16 * SA * 2) + ksb);
                #pragma unroll
                for (int sub = 0; sub < 2; sub++) {
                    int nt = p * 2 + sub;
                    #pragma unroll
                    for (int mt = 0; mt < 2; mt++) {
                        mma_f16(acc[mt][nt], ah[mt], bh[2 * sub], bh[2 * sub + 1]);
                        mma_f16(acc[mt][nt], ah[mt], bl[2 * sub], bl[2 * sub + 1]);
                    }
                }
            }
        }
        __syncthreads();
    }

    // ---- epilogue: write h fp16 + fused el/er ----
    int head = blockIdx.y * 2 + wn;
    float2 alv[8], arv[8];
    #pragma unroll
    for (int nt = 0; nt < 8; nt++) {
        int d = nt * 8 + 2 * t;
        alv[nt] = *(const float2*)(al + head * 64 + d);
        arv[nt] = *(const float2*)(ar + head * 64 + d);
    }

    #pragma unroll
    for (int mt = 0; mt < 2; mt++) {
        int r0 = rowBase + wm * 32 + mt * 16 + g;
        int r1 = r0 + 8;
        float el0 = 0.f, er0 = 0.f, el1 = 0.f, er1 = 0.f;
        #pragma unroll
        for (int nt = 0; nt < 8; nt++) {
            int col = nbase + wn * 64 + nt * 8 + 2 * t;
            if (r0 < nrows)
                *(__half2*)(g_hh + (size_t)r0 * 256 + col) =
                    __floats2half2_rn(acc[mt][nt][0], acc[mt][nt][1]);
            if (r1 < nrows)
                *(__half2*)(g_hh + (size_t)r1 * 256 + col) =
                    __floats2half2_rn(acc[mt][nt][2], acc[mt][nt][3]);
            el0 += acc[mt][nt][0] * alv[nt].x + acc[mt][nt][1] * alv[nt].y;
            er0 += acc[mt][nt][0] * arv[nt].x + acc[mt][nt][1] * arv[nt].y;
            el1 += acc[mt][nt][2] * alv[nt].x + acc[mt][nt][3] * alv[nt].y;
            er1 += acc[mt][nt][2] * arv[nt].x + acc[mt][nt][3] * arv[nt].y;
        }
        #pragma unroll
        for (int o = 1; o < 4; o <<= 1) {
            el0 += __shfl_xor_sync(0xffffffffu, el0, o);
            er0 += __shfl_xor_sync(0xffffffffu, er0, o);
            el1 += __shfl_xor_sync(0xffffffffu, el1, o);
            er1 += __shfl_xor_sync(0xffffffffu, er1, o);
        }
        if (t == 0) {
            if (r0 < nrows) { g_el[r0 * 4 + head] = el0; g_er[r0 * 4 + head] = er0; }
            if (r1 < nrows) { g_el[r1 * 4 + head] = el1; g_er[r1 * 4 + head] = er1; }
        }
    }
}

// ---------- fused edge-softmax + aggregation (fp16 gather, 128 thr/node) -----
__global__ __launch_bounds__(128) void aggregate_kernel(
    const float* __restrict__ bias, float* __restrict__ outf, int write_f16)
{
    int n = blockIdx.x;
    int tid = threadIdx.x;
    int hh = tid >> 5;
    int beg = g_off[n], end = g_off[n + 1];

    __shared__ int   s_src[128];
    __shared__ float s_a[128 * 4];

    float4 rn = ((const float4*)g_er)[n];
    float acc0 = 0.f, acc1 = 0.f, den = 0.f;
    const __half2* htab = (const __half2*)g_hh;

    for (int base = beg; base < end; base += 128) {
        int cnt = min(128, end - base);
        __syncthreads();
        for (int i = tid; i < cnt; i += 128) {
            int s = g_csrc[base + i];
            s_src[i] = s;
            float4 l = ((const float4*)g_el)[s];
            float4 w;
            float e0 = l.x + rn.x; e0 = (e0 > 0.f) ? e0 : 0.2f * e0; w.x = __expf(e0);
            float e1 = l.y + rn.y; e1 = (e1 > 0.f) ? e1 : 0.2f * e1; w.y = __expf(e1);
            float e2 = l.z + rn.z; e2 = (e2 > 0.f) ? e2 : 0.2f * e2; w.z = __expf(e2);
            float e3 = l.w + rn.w; e3 = (e3 > 0.f) ? e3 : 0.2f * e3; w.w = __expf(e3);
            ((float4*)s_a)[i] = w;
        }
        __syncthreads();
        int i = 0;
        for (; i + 4 <= cnt; i += 4) {
            float a0 = s_a[(i + 0) * 4 + hh];
            float a1 = s_a[(i + 1) * 4 + hh];
            float a2 = s_a[(i + 2) * 4 + hh];
            float a3 = s_a[(i + 3) * 4 + hh];
            int s0 = s_src[i], s1 = s_src[i + 1], s2 = s_src[i + 2], s3 = s_src[i + 3];
            float2 h0 = __half22float2(htab[(size_t)s0 * 128 + tid]);
            float2 h1 = __half22float2(htab[(size_t)s1 * 128 + tid]);
            float2 h2 = __half22float2(htab[(size_t)s2 * 128 + tid]);
            float2 h3 = __half22float2(htab[(size_t)s3 * 128 + tid]);
            acc0 += a0 * h0.x + a1 * h1.x + a2 * h2.x + a3 * h3.x;
            acc1 += a0 * h0.y + a1 * h1.y + a2 * h2.y + a3 * h3.y;
            den += (a0 + a1) + (a2 + a3);
        }
        for (; i < cnt; i++) {
            float a = s_a[i * 4 + hh];
            float2 hv = __half22float2(htab[(size_t)s_src[i] * 128 + tid]);
            acc0 += a * hv.x;
            acc1 += a * hv.y;
            den += a;
        }
    }
    float inv = 1.f / den;
    float v0 = fmaxf(acc0 * inv + bias[2 * tid], 0.f);
    float v1 = fmaxf(acc1 * inv + bias[2 * tid + 1], 0.f);
    size_t oi = (size_t)n * 256 + 2 * tid;
    if (write_f16) {
        *(__half2*)(g_Ah + oi) = __floats2half2_rn(v0, v1);
    } else {
        *(float2*)(outf + oi) = make_float2(v0, v1);
    }
}

// ---------------- launch ----------------
extern "C" void kernel_launch(void* const* d_in, const int* in_sizes, int n_in,
                              void* d_out, int out_size)
{
    const float* feat = (const float*)d_in[0];
    const int*   src  = (const int*)d_in[1];
    const int*   dst  = (const int*)d_in[2];
    const float* W1   = (const float*)d_in[3];
    const float* al1  = (const float*)d_in[4];
    const float* ar1  = (const float*)d_in[5];
    const float* b1   = (const float*)d_in[6];
    const float* W2   = (const float*)d_in[7];
    const float* al2  = (const float*)d_in[8];
    const float* ar2  = (const float*)d_in[9];
    const float* b2   = (const float*)d_in[10];
    float* out = (float*)d_out;
    int E = in_sizes[1];

    void* p;
    cudaGetSymbolAddress(&p, g_Ah); __half* ah = (__half*)p;

    static int smem_set = 0;
    if (!smem_set) {
        cudaFuncSetAttribute(gemm_mma_kernel,
                             cudaFuncAttributeMaxDynamicSharedMemorySize, GEMM_SMEM);
        smem_set = 1;
    }

    int egrid = (E + 255) / 256;
    int ngrid = (NN + 255) / 256;
    dim3 ggrid((NN + 127) / 128, 2);

    // CSR build (same for both layers)
    zero_indeg_kernel<<<ngrid, 256>>>();
    csr_count_kernel<<<egrid, 256>>>(dst, E);
    scan_kernel<<<1, 1024>>>();
    csr_scatter_kernel<<<egrid, 256>>>(dst, src, E);

    // layer 1
    asplit_kernel<<<NN / 2, 256>>>(feat);
    wsplit_kernel<<<256, 256>>>(W1);
    gemm_mma_kernel<<<ggrid, 256, GEMM_SMEM>>>(ah, al1, ar1, NN);
    aggregate_kernel<<<NN, 128>>>(b1, nullptr, 1);

    // layer 2
    wsplit_kernel<<<256, 256>>>(W2);
    gemm_mma_kernel<<<ggrid, 256, GEMM_SMEM>>>(ah, al2, ar2, NN);
    aggregate_kernel<<<NN, 128>>>(b2, out, 0);
}

// round 9
// speedup vs baseline: 2.1279x; 1.0671x over previous
#include <cuda_runtime.h>
#include <cuda_fp16.h>
#include <cstdint>
#include <cstddef>

#define NN 50000
#define EE 850000
#define HH 4

// ---------------- scratch (static device globals; no runtime alloc) ----------
__device__ __half g_hh[(size_t)NN * 256];     // h in fp16 (gather table)
__device__ float g_el[NN * HH];
__device__ float g_er[NN * HH];
__device__ __align__(16) int g_indeg[NN];
__device__ __align__(16) int g_off[NN + 4];
__device__ __align__(16) int g_cur[NN];
__device__ int   g_csrc[EE];                  // CSR payload: src node id
__device__ __half g_Ah[(size_t)NN * 256];     // GEMM input (fp16)
__device__ __half g_Wt[256 * 256];            // W fp16, transposed [n][k]

// ---------------- PTX helpers ----------------
__device__ __forceinline__ uint32_t smem_u32(const void* p) {
    uint32_t a;
    asm("{ .reg .u64 t; cvta.to.shared.u64 t, %1; cvt.u32.u64 %0, t; }"
        : "=r"(a) : "l"(p));
    return a;
}
#define CP_ASYNC16(dst, src) \
    asm volatile("cp.async.cg.shared.global [%0], [%1], 16;" :: "r"(dst), "l"(src))
#define CP_COMMIT() asm volatile("cp.async.commit_group;" ::: "memory")
#define CP_WAIT(n)  asm volatile("cp.async.wait_group %0;" :: "n"(n) : "memory")

__device__ __forceinline__ void mma_f16(float* c, const uint32_t* a,
                                        uint32_t b0, uint32_t b1) {
    asm volatile(
        "mma.sync.aligned.m16n8k16.row.col.f32.f16.f16.f32 "
        "{%0,%1,%2,%3}, {%4,%5,%6,%7}, {%8,%9}, {%0,%1,%2,%3};"
        : "+f"(c[0]), "+f"(c[1]), "+f"(c[2]), "+f"(c[3])
        : "r"(a[0]), "r"(a[1]), "r"(a[2]), "r"(a[3]), "r"(b0), "r"(b1));
}
__device__ __forceinline__ void ldm_x4(uint32_t* r, uint32_t addr) {
    asm volatile(
        "ldmatrix.sync.aligned.m8n8.x4.shared.b16 {%0,%1,%2,%3}, [%4];"
        : "=r"(r[0]), "=r"(r[1]), "=r"(r[2]), "=r"(r[3]) : "r"(addr));
}

// ---------------- CSR build ----------------
__global__ void zero_indeg_kernel() {
    int i = blockIdx.x * blockDim.x + threadIdx.x;
    if (i < NN) g_indeg[i] = 0;
}

__global__ void csr_count_kernel(const int* __restrict__ dst, int E) {
    int e = blockIdx.x * blockDim.x + threadIdx.x;
    if (e < E) atomicAdd(&g_indeg[dst[e]], 1);
}

__global__ void scan_kernel() {
    __shared__ int warp_sums[32];
    __shared__ int s_carry;
    int tid = threadIdx.x;
    int lane = tid & 31, wid = tid >> 5;
    if (tid == 0) s_carry = 0;
    __syncthreads();
    const int NQ = NN / 4;                     // 12500 int4 groups
    for (int base = 0; base < NQ; base += 1024) {
        int idx = base + tid;
        int4 v = make_int4(0, 0, 0, 0);
        if (idx < NQ) v = ((const int4*)g_indeg)[idx];
        int tot = v.x + v.y + v.z + v.w;
        int x = tot;
        #pragma unroll
        for (int o = 1; o < 32; o <<= 1) {
            int t = __shfl_up_sync(0xffffffffu, x, o);
            if (lane >= o) x += t;
        }
        if (lane == 31) warp_sums[wid] = x;
        __syncthreads();
        if (wid == 0) {
            int ws = warp_sums[lane];
            #pragma unroll
            for (int o = 1; o < 32; o <<= 1) {
                int t = __shfl_up_sync(0xffffffffu, ws, o);
                if (lane >= o) ws += t;
            }
            warp_sums[lane] = ws;
        }
        __syncthreads();
        int warp_excl = (wid == 0) ? 0 : warp_sums[wid - 1];
        int excl = x - tot + warp_excl + s_carry;
        if (idx < NQ) {
            int4 o;
            o.x = excl;
            o.y = o.x + v.x;
            o.z = o.y + v.y;
            o.w = o.z + v.z;
            ((int4*)g_off)[idx] = o;
            ((int4*)g_cur)[idx] = o;
        }
        __syncthreads();
        if (tid == 0) s_carry += warp_sums[31];
        __syncthreads();
    }
    if (threadIdx.x == 0) g_off[NN] = s_carry;
}

__global__ void csr_scatter_kernel(const int* __restrict__ dst,
                                   const int* __restrict__ src, int E) {
    int e = blockIdx.x * blockDim.x + threadIdx.x;
    if (e < E) {
        int p = atomicAdd(&g_cur[dst[e]], 1);
        g_csrc[p] = src[e];
    }
}

// ---------------- splits ----------------
__global__ void wsplit_kernel(const float* __restrict__ W) {
    int idx = blockIdx.x * 256 + threadIdx.x;
    int k = idx >> 8, n = idx & 255;
    g_Wt[n * 256 + k] = __float2half_rn(W[k * 256 + n]);
}

__global__ void asplit_kernel(const float* __restrict__ X) {
    size_t i = ((size_t)blockIdx.x * 256 + threadIdx.x) * 2;
    float2 v = *(const float2*)(X + i);
    *(__half2*)(g_Ah + i) = __floats2half2_rn(v.x, v.y);
}

// --------- fp16 mma.sync GEMM (single term) + fused attn epilogue ------------
// C = A·W^T ; BM=128, BN=128, BK=32; 256 thr = 8 warps (4m x 2n).
#define SA 40
#define ATILE (128 * SA)                 // halves per array (5120) = 10240 B
#define BUFB (2 * ATILE * 2)             // bytes per buffer: A, B = 20480
#define GEMM_SMEM (2 * BUFB)             // 40960 B

__global__ __launch_bounds__(256) void gemm_mma_kernel(
    const __half* __restrict__ A,
    const float* __restrict__ al, const float* __restrict__ ar, int nrows)
{
    extern __shared__ __half sm[];
    int tid = threadIdx.x;
    int lane = tid & 31;
    int wid = tid >> 5;
    int wm = wid & 3, wn = wid >> 2;
    int g = lane >> 2, t = lane & 3;
    int rowBase = blockIdx.x * 128;
    int nbase = blockIdx.y * 128;

    uint32_t sb = smem_u32(sm);

    uint32_t aOff = (uint32_t)(((wm * 32 + (lane & 15)) * SA + ((lane >> 4) << 3)) * 2);
    uint32_t bOff = (uint32_t)(((wn * 64 + ((lane >> 4) << 3) + (lane & 7)) * SA +
                                (((lane >> 3) & 1) << 3)) * 2);

    float acc[2][8][4];
    #pragma unroll
    for (int mt = 0; mt < 2; mt++)
        #pragma unroll
        for (int nt = 0; nt < 8; nt++)
            #pragma unroll
            for (int q = 0; q < 4; q++) acc[mt][nt][q] = 0.f;

    #define STAGE(buf, k0)                                                        \
    do {                                                                          \
        uint32_t base = sb + (uint32_t)(buf) * BUFB;                              \
        _Pragma("unroll")                                                         \
        for (int p = 0; p < 2; p++) {                                             \
            int c = tid + p * 256;                                                \
            int r = c >> 2, j = c & 3;                                            \
            uint32_t so = (uint32_t)(r * (SA * 2) + j * 16);                      \
            int arow = rowBase + r;                                               \
            if (arow < nrows)                                                     \
                CP_ASYNC16(base + so, A + (size_t)arow * 256 + (k0) + j * 8);     \
            CP_ASYNC16(base + ATILE * 2 + so,                                     \
                       g_Wt + (size_t)(nbase + r) * 256 + (k0) + j * 8);          \
        }                                                                         \
        CP_COMMIT();                                                              \
    } while (0)

    STAGE(0, 0);

    #pragma unroll
    for (int kt = 0; kt < 8; kt++) {
        if (kt < 7) STAGE((kt + 1) & 1, (kt + 1) * 32);
        if (kt < 7) { CP_WAIT(1); } else { CP_WAIT(0); }
        __syncthreads();

        uint32_t bufb = sb + (uint32_t)(kt & 1) * BUFB;
        uint32_t aP = bufb + aOff;
        uint32_t bP = bufb + ATILE * 2 + bOff;

        #pragma unroll
        for (int kk = 0; kk < 2; kk++) {
            uint32_t ksb = (uint32_t)(kk * 32);
            uint32_t ah[2][4];
            #pragma unroll
            for (int mt = 0; mt < 2; mt++)
                ldm_x4(ah[mt], aP + (uint32_t)(mt * 16 * SA * 2) + ksb);
            #pragma unroll
            for (int p = 0; p < 4; p++) {
                uint32_t bh[4];
                ldm_x4(bh, bP + (uint32_t)(p * 16 * SA * 2) + ksb);
                #pragma unroll
                for (int sub = 0; sub < 2; sub++) {
                    int nt = p * 2 + sub;
                    #pragma unroll
                    for (int mt = 0; mt < 2; mt++)
                        mma_f16(acc[mt][nt], ah[mt], bh[2 * sub], bh[2 * sub + 1]);
                }
            }
        }
        __syncthreads();
    }

    // ---- epilogue: write h fp16 + fused el/er ----
    int head = blockIdx.y * 2 + wn;
    float2 alv[8], arv[8];
    #pragma unroll
    for (int nt = 0; nt < 8; nt++) {
        int d = nt * 8 + 2 * t;
        alv[nt] = *(const float2*)(al + head * 64 + d);
        arv[nt] = *(const float2*)(ar + head * 64 + d);
    }

    #pragma unroll
    for (int mt = 0; mt < 2; mt++) {
        int r0 = rowBase + wm * 32 + mt * 16 + g;
        int r1 = r0 + 8;
        float el0 = 0.f, er0 = 0.f, el1 = 0.f, er1 = 0.f;
        #pragma unroll
        for (int nt = 0; nt < 8; nt++) {
            int col = nbase + wn * 64 + nt * 8 + 2 * t;
            if (r0 < nrows)
                *(__half2*)(g_hh + (size_t)r0 * 256 + col) =
                    __floats2half2_rn(acc[mt][nt][0], acc[mt][nt][1]);
            if (r1 < nrows)
                *(__half2*)(g_hh + (size_t)r1 * 256 + col) =
                    __floats2half2_rn(acc[mt][nt][2], acc[mt][nt][3]);
            el0 += acc[mt][nt][0] * alv[nt].x + acc[mt][nt][1] * alv[nt].y;
            er0 += acc[mt][nt][0] * arv[nt].x + acc[mt][nt][1] * arv[nt].y;
            el1 += acc[mt][nt][2] * alv[nt].x + acc[mt][nt][3] * alv[nt].y;
            er1 += acc[mt][nt][2] * arv[nt].x + acc[mt][nt][3] * arv[nt].y;
        }
        #pragma unroll
        for (int o = 1; o < 4; o <<= 1) {
            el0 += __shfl_xor_sync(0xffffffffu, el0, o);
            er0 += __shfl_xor_sync(0xffffffffu, er0, o);
            el1 += __shfl_xor_sync(0xffffffffu, el1, o);
            er1 += __shfl_xor_sync(0xffffffffu, er1, o);
        }
        if (t == 0) {
            if (r0 < nrows) { g_el[r0 * 4 + head] = el0; g_er[r0 * 4 + head] = er0; }
            if (r1 < nrows) { g_el[r1 * 4 + head] = el1; g_er[r1 * 4 + head] = er1; }
        }
    }
}

// ---------- fused edge-softmax + aggregation (fp16 gather, 128 thr/node) -----
__global__ __launch_bounds__(128) void aggregate_kernel(
    const float* __restrict__ bias, float* __restrict__ outf, int write_f16)
{
    int n = blockIdx.x;
    int tid = threadIdx.x;
    int hh = tid >> 5;
    int beg = g_off[n], end = g_off[n + 1];

    __shared__ int   s_src[128];
    __shared__ float s_a[128 * 4];

    float4 rn = ((const float4*)g_er)[n];
    float acc0 = 0.f, acc1 = 0.f, den = 0.f;
    const __half2* htab = (const __half2*)g_hh;

    for (int base = beg; base < end; base += 128) {
        int cnt = min(128, end - base);
        __syncthreads();
        for (int i = tid; i < cnt; i += 128) {
            int s = g_csrc[base + i];
            s_src[i] = s;
            float4 l = ((const float4*)g_el)[s];
            float4 w;
            float e0 = l.x + rn.x; e0 = (e0 > 0.f) ? e0 : 0.2f * e0; w.x = __expf(e0);
            float e1 = l.y + rn.y; e1 = (e1 > 0.f) ? e1 : 0.2f * e1; w.y = __expf(e1);
            float e2 = l.z + rn.z; e2 = (e2 > 0.f) ? e2 : 0.2f * e2; w.z = __expf(e2);
            float e3 = l.w + rn.w; e3 = (e3 > 0.f) ? e3 : 0.2f * e3; w.w = __expf(e3);
            ((float4*)s_a)[i] = w;
        }
        __syncthreads();
        int i = 0;
        for (; i + 4 <= cnt; i += 4) {
            float a0 = s_a[(i + 0) * 4 + hh];
            float a1 = s_a[(i + 1) * 4 + hh];
            float a2 = s_a[(i + 2) * 4 + hh];
            float a3 = s_a[(i + 3) * 4 + hh];
            int s0 = s_src[i], s1 = s_src[i + 1], s2 = s_src[i + 2], s3 = s_src[i + 3];
            float2 h0 = __half22float2(htab[(size_t)s0 * 128 + tid]);
            float2 h1 = __half22float2(htab[(size_t)s1 * 128 + tid]);
            float2 h2 = __half22float2(htab[(size_t)s2 * 128 + tid]);
            float2 h3 = __half22float2(htab[(size_t)s3 * 128 + tid]);
            acc0 += a0 * h0.x + a1 * h1.x + a2 * h2.x + a3 * h3.x;
            acc1 += a0 * h0.y + a1 * h1.y + a2 * h2.y + a3 * h3.y;
            den += (a0 + a1) + (a2 + a3);
        }
        for (; i < cnt; i++) {
            float a = s_a[i * 4 + hh];
            float2 hv = __half22float2(htab[(size_t)s_src[i] * 128 + tid]);
            acc0 += a * hv.x;
            acc1 += a * hv.y;
            den += a;
        }
    }
    float inv = 1.f / den;
    float v0 = fmaxf(acc0 * inv + bias[2 * tid], 0.f);
    float v1 = fmaxf(acc1 * inv + bias[2 * tid + 1], 0.f);
    size_t oi = (size_t)n * 256 + 2 * tid;
    if (write_f16) {
        *(__half2*)(g_Ah + oi) = __floats2half2_rn(v0, v1);
    } else {
        *(float2*)(outf + oi) = make_float2(v0, v1);
    }
}

// ---------------- launch ----------------
extern "C" void kernel_launch(void* const* d_in, const int* in_sizes, int n_in,
                              void* d_out, int out_size)
{
    const float* feat = (const float*)d_in[0];
    const int*   src  = (const int*)d_in[1];
    const int*   dst  = (const int*)d_in[2];
    const float* W1   = (const float*)d_in[3];
    const float* al1  = (const float*)d_in[4];
    const float* ar1  = (const float*)d_in[5];
    const float* b1   = (const float*)d_in[6];
    const float* W2   = (const float*)d_in[7];
    const float* al2  = (const float*)d_in[8];
    const float* ar2  = (const float*)d_in[9];
    const float* b2   = (const float*)d_in[10];
    float* out = (float*)d_out;
    int E = in_sizes[1];

    void* p;
    cudaGetSymbolAddress(&p, g_Ah); __half* ah = (__half*)p;

    static int smem_set = 0;
    if (!smem_set) {
        cudaFuncSetAttribute(gemm_mma_kernel,
                             cudaFuncAttributeMaxDynamicSharedMemorySize, GEMM_SMEM);
        smem_set = 1;
    }

    int egrid = (E + 255) / 256;
    int ngrid = (NN + 255) / 256;
    dim3 ggrid((NN + 127) / 128, 2);

    // CSR build (same for both layers)
    zero_indeg_kernel<<<ngrid, 256>>>();
    csr_count_kernel<<<egrid, 256>>>(dst, E);
    scan_kernel<<<1, 1024>>>();
    csr_scatter_kernel<<<egrid, 256>>>(dst, src, E);

    // layer 1
    asplit_kernel<<<NN / 2, 256>>>(feat);
    wsplit_kernel<<<256, 256>>>(W1);
    gemm_mma_kernel<<<ggrid, 256, GEMM_SMEM>>>(ah, al1, ar1, NN);
    aggregate_kernel<<<NN, 128>>>(b1, nullptr, 1);

    // layer 2
    wsplit_kernel<<<256, 256>>>(W2);
    gemm_mma_kernel<<<ggrid, 256, GEMM_SMEM>>>(ah, al2, ar2, NN);
    aggregate_kernel<<<NN, 128>>>(b2, out, 0);
}

// round 10
// speedup vs baseline: 2.3141x; 1.0875x over previous
#include <cuda_runtime.h>
#include <cuda_fp16.h>
#include <cstdint>
#include <cstddef>

#define NN 50000
#define EE 850000
#define HH 4

// ---------------- scratch (static device globals; no runtime alloc) ----------
__device__ __half g_hh[(size_t)NN * 256];     // h in fp16 (gather table)
__device__ float g_el[NN * HH];
__device__ float g_er[NN * HH];
__device__ __align__(16) int g_indeg[NN];
__device__ __align__(16) int g_off[NN + 4];
__device__ __align__(16) int g_cur[NN];
__device__ int   g_csrc[EE];                  // CSR payload: src node id
__device__ __half g_Ah[(size_t)NN * 256];     // GEMM input (fp16)
__device__ __half g_Wt1[256 * 256];           // W1 fp16, transposed [n][k]
__device__ __half g_Wt2[256 * 256];           // W2 fp16, transposed [n][k]

// ---------------- PTX helpers ----------------
__device__ __forceinline__ uint32_t smem_u32(const void* p) {
    uint32_t a;
    asm("{ .reg .u64 t; cvta.to.shared.u64 t, %1; cvt.u32.u64 %0, t; }"
        : "=r"(a) : "l"(p));
    return a;
}
#define CP_ASYNC16(dst, src) \
    asm volatile("cp.async.cg.shared.global [%0], [%1], 16;" :: "r"(dst), "l"(src))
#define CP_COMMIT() asm volatile("cp.async.commit_group;" ::: "memory")
#define CP_WAIT(n)  asm volatile("cp.async.wait_group %0;" :: "n"(n) : "memory")

__device__ __forceinline__ void mma_f16(float* c, const uint32_t* a,
                                        uint32_t b0, uint32_t b1) {
    asm volatile(
        "mma.sync.aligned.m16n8k16.row.col.f32.f16.f16.f32 "
        "{%0,%1,%2,%3}, {%4,%5,%6,%7}, {%8,%9}, {%0,%1,%2,%3};"
        : "+f"(c[0]), "+f"(c[1]), "+f"(c[2]), "+f"(c[3])
        : "r"(a[0]), "r"(a[1]), "r"(a[2]), "r"(a[3]), "r"(b0), "r"(b1));
}
__device__ __forceinline__ void ldm_x4(uint32_t* r, uint32_t addr) {
    asm volatile(
        "ldmatrix.sync.aligned.m8n8.x4.shared.b16 {%0,%1,%2,%3}, [%4];"
        : "=r"(r[0]), "=r"(r[1]), "=r"(r[2]), "=r"(r[3]) : "r"(addr));
}

// ---------------- CSR build ----------------
__global__ void zero_indeg_kernel() {
    int i = blockIdx.x * blockDim.x + threadIdx.x;
    if (i < NN) g_indeg[i] = 0;
}

__global__ void csr_count_kernel(const int* __restrict__ dst, int E) {
    int e = blockIdx.x * blockDim.x + threadIdx.x;
    if (e < E) atomicAdd(&g_indeg[dst[e]], 1);
}

__global__ void scan_kernel() {
    __shared__ int warp_sums[32];
    __shared__ int s_carry;
    int tid = threadIdx.x;
    int lane = tid & 31, wid = tid >> 5;
    if (tid == 0) s_carry = 0;
    __syncthreads();
    const int NQ = NN / 4;                     // 12500 int4 groups
    for (int base = 0; base < NQ; base += 1024) {
        int idx = base + tid;
        int4 v = make_int4(0, 0, 0, 0);
        if (idx < NQ) v = ((const int4*)g_indeg)[idx];
        int tot = v.x + v.y + v.z + v.w;
        int x = tot;
        #pragma unroll
        for (int o = 1; o < 32; o <<= 1) {
            int t = __shfl_up_sync(0xffffffffu, x, o);
            if (lane >= o) x += t;
        }
        if (lane == 31) warp_sums[wid] = x;
        __syncthreads();
        if (wid == 0) {
            int ws = warp_sums[lane];
            #pragma unroll
            for (int o = 1; o < 32; o <<= 1) {
                int t = __shfl_up_sync(0xffffffffu, ws, o);
                if (lane >= o) ws += t;
            }
            warp_sums[lane] = ws;
        }
        __syncthreads();
        int warp_excl = (wid == 0) ? 0 : warp_sums[wid - 1];
        int excl = x - tot + warp_excl + s_carry;
        if (idx < NQ) {
            int4 o;
            o.x = excl;
            o.y = o.x + v.x;
            o.z = o.y + v.y;
            o.w = o.z + v.z;
            ((int4*)g_off)[idx] = o;
            ((int4*)g_cur)[idx] = o;
        }
        __syncthreads();
        if (tid == 0) s_carry += warp_sums[31];
        __syncthreads();
    }
    if (threadIdx.x == 0) g_off[NN] = s_carry;
}

__global__ void csr_scatter_kernel(const int* __restrict__ dst,
                                   const int* __restrict__ src, int E) {
    int e = blockIdx.x * blockDim.x + threadIdx.x;
    if (e < E) {
        int p = atomicAdd(&g_cur[dst[e]], 1);
        g_csrc[p] = src[e];
    }
}

// ---------------- splits ----------------
__global__ void wsplit_kernel(const float* __restrict__ W, __half* __restrict__ Wt) {
    int idx = blockIdx.x * 256 + threadIdx.x;
    int k = idx >> 8, n = idx & 255;
    Wt[n * 256 + k] = __float2half_rn(W[k * 256 + n]);
}

__global__ void asplit_kernel(const float* __restrict__ X) {
    size_t i = ((size_t)blockIdx.x * 256 + threadIdx.x) * 2;
    float2 v = *(const float2*)(X + i);
    *(__half2*)(g_Ah + i) = __floats2half2_rn(v.x, v.y);
}

// --------- fp16 mma.sync GEMM (single term) + fused attn epilogue ------------
#define SA 40
#define ATILE (128 * SA)
#define BUFB (2 * ATILE * 2)
#define GEMM_SMEM (2 * BUFB)

__global__ __launch_bounds__(256) void gemm_mma_kernel(
    const __half* __restrict__ A, const __half* __restrict__ Wt,
    const float* __restrict__ al, const float* __restrict__ ar, int nrows)
{
    extern __shared__ __half sm[];
    int tid = threadIdx.x;
    int lane = tid & 31;
    int wid = tid >> 5;
    int wm = wid & 3, wn = wid >> 2;
    int g = lane >> 2, t = lane & 3;
    int rowBase = blockIdx.x * 128;
    int nbase = blockIdx.y * 128;

    uint32_t sb = smem_u32(sm);

    uint32_t aOff = (uint32_t)(((wm * 32 + (lane & 15)) * SA + ((lane >> 4) << 3)) * 2);
    uint32_t bOff = (uint32_t)(((wn * 64 + ((lane >> 4) << 3) + (lane & 7)) * SA +
                                (((lane >> 3) & 1) << 3)) * 2);

    float acc[2][8][4];
    #pragma unroll
    for (int mt = 0; mt < 2; mt++)
        #pragma unroll
        for (int nt = 0; nt < 8; nt++)
            #pragma unroll
            for (int q = 0; q < 4; q++) acc[mt][nt][q] = 0.f;

    #define STAGE(buf, k0)                                                        \
    do {                                                                          \
        uint32_t base = sb + (uint32_t)(buf) * BUFB;                              \
        _Pragma("unroll")                                                         \
        for (int p = 0; p < 2; p++) {                                             \
            int c = tid + p * 256;                                                \
            int r = c >> 2, j = c & 3;                                            \
            uint32_t so = (uint32_t)(r * (SA * 2) + j * 16);                      \
            int arow = rowBase + r;                                               \
            if (arow < nrows)                                                     \
                CP_ASYNC16(base + so, A + (size_t)arow * 256 + (k0) + j * 8);     \
            CP_ASYNC16(base + ATILE * 2 + so,                                     \
                       Wt + (size_t)(nbase + r) * 256 + (k0) + j * 8);            \
        }                                                                         \
        CP_COMMIT();                                                              \
    } while (0)

    STAGE(0, 0);

    #pragma unroll
    for (int kt = 0; kt < 8; kt++) {
        if (kt < 7) STAGE((kt + 1) & 1, (kt + 1) * 32);
        if (kt < 7) { CP_WAIT(1); } else { CP_WAIT(0); }
        __syncthreads();

        uint32_t bufb = sb + (uint32_t)(kt & 1) * BUFB;
        uint32_t aP = bufb + aOff;
        uint32_t bP = bufb + ATILE * 2 + bOff;

        #pragma unroll
        for (int kk = 0; kk < 2; kk++) {
            uint32_t ksb = (uint32_t)(kk * 32);
            uint32_t ah[2][4];
            #pragma unroll
            for (int mt = 0; mt < 2; mt++)
                ldm_x4(ah[mt], aP + (uint32_t)(mt * 16 * SA * 2) + ksb);
            #pragma unroll
            for (int p = 0; p < 4; p++) {
                uint32_t bh[4];
                ldm_x4(bh, bP + (uint32_t)(p * 16 * SA * 2) + ksb);
                #pragma unroll
                for (int sub = 0; sub < 2; sub++) {
                    int nt = p * 2 + sub;
                    #pragma unroll
                    for (int mt = 0; mt < 2; mt++)
                        mma_f16(acc[mt][nt], ah[mt], bh[2 * sub], bh[2 * sub + 1]);
                }
            }
        }
        __syncthreads();
    }

    // ---- epilogue: write h fp16 + fused el/er ----
    int head = blockIdx.y * 2 + wn;
    float2 alv[8], arv[8];
    #pragma unroll
    for (int nt = 0; nt < 8; nt++) {
        int d = nt * 8 + 2 * t;
        alv[nt] = *(const float2*)(al + head * 64 + d);
        arv[nt] = *(const float2*)(ar + head * 64 + d);
    }

    #pragma unroll
    for (int mt = 0; mt < 2; mt++) {
        int r0 = rowBase + wm * 32 + mt * 16 + g;
        int r1 = r0 + 8;
        float el0 = 0.f, er0 = 0.f, el1 = 0.f, er1 = 0.f;
        #pragma unroll
        for (int nt = 0; nt < 8; nt++) {
            int col = nbase + wn * 64 + nt * 8 + 2 * t;
            if (r0 < nrows)
                *(__half2*)(g_hh + (size_t)r0 * 256 + col) =
                    __floats2half2_rn(acc[mt][nt][0], acc[mt][nt][1]);
            if (r1 < nrows)
                *(__half2*)(g_hh + (size_t)r1 * 256 + col) =
                    __floats2half2_rn(acc[mt][nt][2], acc[mt][nt][3]);
            el0 += acc[mt][nt][0] * alv[nt].x + acc[mt][nt][1] * alv[nt].y;
            er0 += acc[mt][nt][0] * arv[nt].x + acc[mt][nt][1] * arv[nt].y;
            el1 += acc[mt][nt][2] * alv[nt].x + acc[mt][nt][3] * alv[nt].y;
            er1 += acc[mt][nt][2] * arv[nt].x + acc[mt][nt][3] * arv[nt].y;
        }
        #pragma unroll
        for (int o = 1; o < 4; o <<= 1) {
            el0 += __shfl_xor_sync(0xffffffffu, el0, o);
            er0 += __shfl_xor_sync(0xffffffffu, er0, o);
            el1 += __shfl_xor_sync(0xffffffffu, el1, o);
            er1 += __shfl_xor_sync(0xffffffffu, er1, o);
        }
        if (t == 0) {
            if (r0 < nrows) { g_el[r0 * 4 + head] = el0; g_er[r0 * 4 + head] = er0; }
            if (r1 < nrows) { g_el[r1 * 4 + head] = el1; g_er[r1 * 4 + head] = er1; }
        }
    }
}

// ---------- fused edge-softmax + aggregation (fp16 gather, 128 thr/node) -----
__global__ __launch_bounds__(128) void aggregate_kernel(
    const float* __restrict__ bias, float* __restrict__ outf, int write_f16)
{
    int n = blockIdx.x;
    int tid = threadIdx.x;
    int hh = tid >> 5;
    int beg = g_off[n], end = g_off[n + 1];

    __shared__ int   s_src[128];
    __shared__ float s_a[128 * 4];

    float4 rn = ((const float4*)g_er)[n];
    float acc0 = 0.f, acc1 = 0.f, den = 0.f;
    const __half2* htab = (const __half2*)g_hh;

    for (int base = beg; base < end; base += 128) {
        int cnt = min(128, end - base);
        __syncthreads();
        for (int i = tid; i < cnt; i += 128) {
            int s = g_csrc[base + i];
            s_src[i] = s;
            float4 l = ((const float4*)g_el)[s];
            float4 w;
            float e0 = l.x + rn.x; e0 = (e0 > 0.f) ? e0 : 0.2f * e0; w.x = __expf(e0);
            float e1 = l.y + rn.y; e1 = (e1 > 0.f) ? e1 : 0.2f * e1; w.y = __expf(e1);
            float e2 = l.z + rn.z; e2 = (e2 > 0.f) ? e2 : 0.2f * e2; w.z = __expf(e2);
            float e3 = l.w + rn.w; e3 = (e3 > 0.f) ? e3 : 0.2f * e3; w.w = __expf(e3);
            ((float4*)s_a)[i] = w;
        }
        __syncthreads();
        int i = 0;
        for (; i + 4 <= cnt; i += 4) {
            float a0 = s_a[(i + 0) * 4 + hh];
            float a1 = s_a[(i + 1) * 4 + hh];
            float a2 = s_a[(i + 2) * 4 + hh];
            float a3 = s_a[(i + 3) * 4 + hh];
            int s0 = s_src[i], s1 = s_src[i + 1], s2 = s_src[i + 2], s3 = s_src[i + 3];
            float2 h0 = __half22float2(htab[(size_t)s0 * 128 + tid]);
            float2 h1 = __half22float2(htab[(size_t)s1 * 128 + tid]);
            float2 h2 = __half22float2(htab[(size_t)s2 * 128 + tid]);
            float2 h3 = __half22float2(htab[(size_t)s3 * 128 + tid]);
            acc0 += a0 * h0.x + a1 * h1.x + a2 * h2.x + a3 * h3.x;
            acc1 += a0 * h0.y + a1 * h1.y + a2 * h2.y + a3 * h3.y;
            den += (a0 + a1) + (a2 + a3);
        }
        for (; i < cnt; i++) {
            float a = s_a[i * 4 + hh];
            float2 hv = __half22float2(htab[(size_t)s_src[i] * 128 + tid]);
            acc0 += a * hv.x;
            acc1 += a * hv.y;
            den += a;
        }
    }
    float inv = 1.f / den;
    float v0 = fmaxf(acc0 * inv + bias[2 * tid], 0.f);
    float v1 = fmaxf(acc1 * inv + bias[2 * tid + 1], 0.f);
    size_t oi = (size_t)n * 256 + 2 * tid;
    if (write_f16) {
        *(__half2*)(g_Ah + oi) = __floats2half2_rn(v0, v1);
    } else {
        *(float2*)(outf + oi) = make_float2(v0, v1);
    }
}

// ---------------- launch ----------------
extern "C" void kernel_launch(void* const* d_in, const int* in_sizes, int n_in,
                              void* d_out, int out_size)
{
    const float* feat = (const float*)d_in[0];
    const int*   src  = (const int*)d_in[1];
    const int*   dst  = (const int*)d_in[2];
    const float* W1   = (const float*)d_in[3];
    const float* al1  = (const float*)d_in[4];
    const float* ar1  = (const float*)d_in[5];
    const float* b1   = (const float*)d_in[6];
    const float* W2   = (const float*)d_in[7];
    const float* al2  = (const float*)d_in[8];
    const float* ar2  = (const float*)d_in[9];
    const float* b2   = (const float*)d_in[10];
    float* out = (float*)d_out;
    int E = in_sizes[1];

    void* p;
    cudaGetSymbolAddress(&p, g_Ah);  __half* ah  = (__half*)p;
    cudaGetSymbolAddress(&p, g_Wt1); __half* wt1 = (__half*)p;
    cudaGetSymbolAddress(&p, g_Wt2); __half* wt2 = (__half*)p;

    static cudaStream_t s2 = nullptr;
    static cudaEvent_t evFork = nullptr, evJoin = nullptr;
    static int init_done = 0;
    if (!init_done) {
        cudaFuncSetAttribute(gemm_mma_kernel,
                             cudaFuncAttributeMaxDynamicSharedMemorySize, GEMM_SMEM);
        cudaStreamCreateWithFlags(&s2, cudaStreamNonBlocking);
        cudaEventCreateWithFlags(&evFork, cudaEventDisableTiming);
        cudaEventCreateWithFlags(&evJoin, cudaEventDisableTiming);
        init_done = 1;
    }

    int egrid = (E + 255) / 256;
    int ngrid = (NN + 255) / 256;
    dim3 ggrid((NN + 127) / 128, 2);

    // fork: CSR build on side stream, concurrent with splits + GEMM-1
    cudaEventRecord(evFork, 0);
    cudaStreamWaitEvent(s2, evFork, 0);
    zero_indeg_kernel<<<ngrid, 256, 0, s2>>>();
    csr_count_kernel<<<egrid, 256, 0, s2>>>(dst, E);
    scan_kernel<<<1, 1024, 0, s2>>>();
    csr_scatter_kernel<<<egrid, 256, 0, s2>>>(dst, src, E);
    cudaEventRecord(evJoin, s2);

    // main stream: feature convert + both weight tables + GEMM-1
    asplit_kernel<<<NN / 2, 256>>>(feat);
    wsplit_kernel<<<256, 256>>>(W1, wt1);
    wsplit_kernel<<<256, 256>>>(W2, wt2);
    gemm_mma_kernel<<<ggrid, 256, GEMM_SMEM>>>(ah, wt1, al1, ar1, NN);

    // join: aggregate needs CSR
    cudaStreamWaitEvent(0, evJoin, 0);
    aggregate_kernel<<<NN, 128>>>(b1, nullptr, 1);

    // layer 2
    gemm_mma_kernel<<<ggrid, 256, GEMM_SMEM>>>(ah, wt2, al2, ar2, NN);
    aggregate_kernel<<<NN, 128>>>(b2, out, 0);
}

// round 11
// speedup vs baseline: 3.1137x; 1.3456x over previous
#include <cuda_runtime.h>
#include <cuda_fp16.h>
#include <cstdint>
#include <cstddef>

#define NN 50000
#define EE 850000
#define HH 4

// ---------------- scratch (static device globals; no runtime alloc) ----------
__device__ __half g_hh[(size_t)NN * 256];     // h in fp16 (gather table)
__device__ float g_el[NN * HH];
__device__ float g_er[NN * HH];
__device__ __align__(16) int g_indeg[NN];
__device__ __align__(16) int g_off[NN + 4];
__device__ __align__(16) int g_cur[NN];
__device__ int   g_csrc[EE];                  // CSR payload: src node id
__device__ __half g_Ah[(size_t)NN * 256];     // GEMM input (fp16)
__device__ __half g_Wt1[256 * 256];           // W1 fp16, transposed [n][k]
__device__ __half g_Wt2[256 * 256];           // W2 fp16, transposed [n][k]

// ---------------- PTX helpers ----------------
__device__ __forceinline__ uint32_t smem_u32(const void* p) {
    uint32_t a;
    asm("{ .reg .u64 t; cvta.to.shared.u64 t, %1; cvt.u32.u64 %0, t; }"
        : "=r"(a) : "l"(p));
    return a;
}
#define CP_ASYNC16(dst, src) \
    asm volatile("cp.async.cg.shared.global [%0], [%1], 16;" :: "r"(dst), "l"(src))
#define CP_COMMIT() asm volatile("cp.async.commit_group;" ::: "memory")
#define CP_WAIT(n)  asm volatile("cp.async.wait_group %0;" :: "n"(n) : "memory")

__device__ __forceinline__ void mma_f16(float* c, const uint32_t* a,
                                        uint32_t b0, uint32_t b1) {
    asm volatile(
        "mma.sync.aligned.m16n8k16.row.col.f32.f16.f16.f32 "
        "{%0,%1,%2,%3}, {%4,%5,%6,%7}, {%8,%9}, {%0,%1,%2,%3};"
        : "+f"(c[0]), "+f"(c[1]), "+f"(c[2]), "+f"(c[3])
        : "r"(a[0]), "r"(a[1]), "r"(a[2]), "r"(a[3]), "r"(b0), "r"(b1));
}
__device__ __forceinline__ void ldm_x4(uint32_t* r, uint32_t addr) {
    asm volatile(
        "ldmatrix.sync.aligned.m8n8.x4.shared.b16 {%0,%1,%2,%3}, [%4];"
        : "=r"(r[0]), "=r"(r[1]), "=r"(r[2]), "=r"(r[3]) : "r"(addr));
}

// ---------------- CSR build ----------------
__global__ void zero_indeg_kernel() {
    int i = blockIdx.x * blockDim.x + threadIdx.x;
    if (i < NN) g_indeg[i] = 0;
}

__global__ void csr_count_kernel(const int* __restrict__ dst, int E) {
    int e = blockIdx.x * blockDim.x + threadIdx.x;
    if (e < E) atomicAdd(&g_indeg[dst[e]], 1);
}

__global__ void scan_kernel() {
    __shared__ int warp_sums[32];
    __shared__ int s_carry;
    int tid = threadIdx.x;
    int lane = tid & 31, wid = tid >> 5;
    if (tid == 0) s_carry = 0;
    __syncthreads();
    const int NQ = NN / 4;
    for (int base = 0; base < NQ; base += 1024) {
        int idx = base + tid;
        int4 v = make_int4(0, 0, 0, 0);
        if (idx < NQ) v = ((const int4*)g_indeg)[idx];
        int tot = v.x + v.y + v.z + v.w;
        int x = tot;
        #pragma unroll
        for (int o = 1; o < 32; o <<= 1) {
            int t = __shfl_up_sync(0xffffffffu, x, o);
            if (lane >= o) x += t;
        }
        if (lane == 31) warp_sums[wid] = x;
        __syncthreads();
        if (wid == 0) {
            int ws = warp_sums[lane];
            #pragma unroll
            for (int o = 1; o < 32; o <<= 1) {
                int t = __shfl_up_sync(0xffffffffu, ws, o);
                if (lane >= o) ws += t;
            }
            warp_sums[lane] = ws;
        }
        __syncthreads();
        int warp_excl = (wid == 0) ? 0 : warp_sums[wid - 1];
        int excl = x - tot + warp_excl + s_carry;
        if (idx < NQ) {
            int4 o;
            o.x = excl;
            o.y = o.x + v.x;
            o.z = o.y + v.y;
            o.w = o.z + v.z;
            ((int4*)g_off)[idx] = o;
            ((int4*)g_cur)[idx] = o;
        }
        __syncthreads();
        if (tid == 0) s_carry += warp_sums[31];
        __syncthreads();
    }
    if (threadIdx.x == 0) g_off[NN] = s_carry;
}

__global__ void csr_scatter_kernel(const int* __restrict__ dst,
                                   const int* __restrict__ src, int E) {
    int e = blockIdx.x * blockDim.x + threadIdx.x;
    if (e < E) {
        int p = atomicAdd(&g_cur[dst[e]], 1);
        g_csrc[p] = src[e];
    }
}

// ---------------- splits ----------------
__global__ void wsplit_kernel(const float* __restrict__ W, __half* __restrict__ Wt) {
    int idx = blockIdx.x * 256 + threadIdx.x;
    int k = idx >> 8, n = idx & 255;
    Wt[n * 256 + k] = __float2half_rn(W[k * 256 + n]);
}

__global__ void asplit_kernel(const float* __restrict__ X) {
    size_t i = ((size_t)blockIdx.x * 256 + threadIdx.x) * 2;
    float2 v = *(const float2*)(X + i);
    *(__half2*)(g_Ah + i) = __floats2half2_rn(v.x, v.y);
}

// --------- fp16 mma.sync GEMM (single term) + fused attn epilogue ------------
#define SA 40
#define ATILE (128 * SA)
#define BUFB (2 * ATILE * 2)
#define GEMM_SMEM (2 * BUFB)

__global__ __launch_bounds__(256) void gemm_mma_kernel(
    const __half* __restrict__ A, const __half* __restrict__ Wt,
    const float* __restrict__ al, const float* __restrict__ ar, int nrows)
{
    extern __shared__ __half sm[];
    int tid = threadIdx.x;
    int lane = tid & 31;
    int wid = tid >> 5;
    int wm = wid & 3, wn = wid >> 2;
    int g = lane >> 2, t = lane & 3;
    int rowBase = blockIdx.x * 128;
    int nbase = blockIdx.y * 128;

    uint32_t sb = smem_u32(sm);

    uint32_t aOff = (uint32_t)(((wm * 32 + (lane & 15)) * SA + ((lane >> 4) << 3)) * 2);
    uint32_t bOff = (uint32_t)(((wn * 64 + ((lane >> 4) << 3) + (lane & 7)) * SA +
                                (((lane >> 3) & 1) << 3)) * 2);

    float acc[2][8][4];
    #pragma unroll
    for (int mt = 0; mt < 2; mt++)
        #pragma unroll
        for (int nt = 0; nt < 8; nt++)
            #pragma unroll
            for (int q = 0; q < 4; q++) acc[mt][nt][q] = 0.f;

    #define STAGE(buf, k0)                                                        \
    do {                                                                          \
        uint32_t base = sb + (uint32_t)(buf) * BUFB;                              \
        _Pragma("unroll")                                                         \
        for (int p = 0; p < 2; p++) {                                             \
            int c = tid + p * 256;                                                \
            int r = c >> 2, j = c & 3;                                            \
            uint32_t so = (uint32_t)(r * (SA * 2) + j * 16);                      \
            int arow = rowBase + r;                                               \
            if (arow < nrows)                                                     \
                CP_ASYNC16(base + so, A + (size_t)arow * 256 + (k0) + j * 8);     \
            CP_ASYNC16(base + ATILE * 2 + so,                                     \
                       Wt + (size_t)(nbase + r) * 256 + (k0) + j * 8);            \
        }                                                                         \
        CP_COMMIT();                                                              \
    } while (0)

    STAGE(0, 0);

    #pragma unroll
    for (int kt = 0; kt < 8; kt++) {
        if (kt < 7) STAGE((kt + 1) & 1, (kt + 1) * 32);
        if (kt < 7) { CP_WAIT(1); } else { CP_WAIT(0); }
        __syncthreads();

        uint32_t bufb = sb + (uint32_t)(kt & 1) * BUFB;
        uint32_t aP = bufb + aOff;
        uint32_t bP = bufb + ATILE * 2 + bOff;

        #pragma unroll
        for (int kk = 0; kk < 2; kk++) {
            uint32_t ksb = (uint32_t)(kk * 32);
            uint32_t ah[2][4];
            #pragma unroll
            for (int mt = 0; mt < 2; mt++)
                ldm_x4(ah[mt], aP + (uint32_t)(mt * 16 * SA * 2) + ksb);
            #pragma unroll
            for (int p = 0; p < 4; p++) {
                uint32_t bh[4];
                ldm_x4(bh, bP + (uint32_t)(p * 16 * SA * 2) + ksb);
                #pragma unroll
                for (int sub = 0; sub < 2; sub++) {
                    int nt = p * 2 + sub;
                    #pragma unroll
                    for (int mt = 0; mt < 2; mt++)
                        mma_f16(acc[mt][nt], ah[mt], bh[2 * sub], bh[2 * sub + 1]);
                }
            }
        }
        __syncthreads();
    }

    // ---- epilogue: write h fp16 + fused el/er ----
    int head = blockIdx.y * 2 + wn;
    float2 alv[8], arv[8];
    #pragma unroll
    for (int nt = 0; nt < 8; nt++) {
        int d = nt * 8 + 2 * t;
        alv[nt] = *(const float2*)(al + head * 64 + d);
        arv[nt] = *(const float2*)(ar + head * 64 + d);
    }

    #pragma unroll
    for (int mt = 0; mt < 2; mt++) {
        int r0 = rowBase + wm * 32 + mt * 16 + g;
        int r1 = r0 + 8;
        float el0 = 0.f, er0 = 0.f, el1 = 0.f, er1 = 0.f;
        #pragma unroll
        for (int nt = 0; nt < 8; nt++) {
            int col = nbase + wn * 64 + nt * 8 + 2 * t;
            if (r0 < nrows)
                *(__half2*)(g_hh + (size_t)r0 * 256 + col) =
                    __floats2half2_rn(acc[mt][nt][0], acc[mt][nt][1]);
            if (r1 < nrows)
                *(__half2*)(g_hh + (size_t)r1 * 256 + col) =
                    __floats2half2_rn(acc[mt][nt][2], acc[mt][nt][3]);
            el0 += acc[mt][nt][0] * alv[nt].x + acc[mt][nt][1] * alv[nt].y;
            er0 += acc[mt][nt][0] * arv[nt].x + acc[mt][nt][1] * arv[nt].y;
            el1 += acc[mt][nt][2] * alv[nt].x + acc[mt][nt][3] * alv[nt].y;
            er1 += acc[mt][nt][2] * arv[nt].x + acc[mt][nt][3] * arv[nt].y;
        }
        #pragma unroll
        for (int o = 1; o < 4; o <<= 1) {
            el0 += __shfl_xor_sync(0xffffffffu, el0, o);
            er0 += __shfl_xor_sync(0xffffffffu, er0, o);
            el1 += __shfl_xor_sync(0xffffffffu, el1, o);
            er1 += __shfl_xor_sync(0xffffffffu, er1, o);
        }
        if (t == 0) {
            if (r0 < nrows) { g_el[r0 * 4 + head] = el0; g_er[r0 * 4 + head] = er0; }
            if (r1 < nrows) { g_el[r1 * 4 + head] = el1; g_er[r1 * 4 + head] = er1; }
        }
    }
}

// ---------- warp-per-node edge-softmax + aggregation (16B/lane gathers) ------
// 8 warps/block, warp w handles node blockIdx.x*8+w; lane owns features
// [lane*8, lane*8+8); head = lane>>3. No block-level syncs.
__global__ __launch_bounds__(256) void aggregate_kernel(
    const float* __restrict__ bias, float* __restrict__ outf, int write_f16)
{
    __shared__ float s_w[8][32][4];
    __shared__ int   s_s[8][32];
    int w = threadIdx.x >> 5, lane = threadIdx.x & 31;
    int n = blockIdx.x * 8 + w;          // NN = 50000 = 6250*8, exact
    int beg = g_off[n], end = g_off[n + 1];
    int head = lane >> 3;

    float4 rn = ((const float4*)g_er)[n];
    float acc[8];
    #pragma unroll
    for (int k = 0; k < 8; k++) acc[k] = 0.f;
    float den = 0.f;
    const __half* htab = g_hh + (size_t)lane * 8;

    for (int base = beg; base < end; base += 32) {
        int m = end - base;
        if (m > 32) m = 32;
        if (lane < m) {
            int s = g_csrc[base + lane];
            float4 l = ((const float4*)g_el)[s];
            float4 wv;
            float e0 = l.x + rn.x; e0 = (e0 > 0.f) ? e0 : 0.2f * e0; wv.x = __expf(e0);
            float e1 = l.y + rn.y; e1 = (e1 > 0.f) ? e1 : 0.2f * e1; wv.y = __expf(e1);
            float e2 = l.z + rn.z; e2 = (e2 > 0.f) ? e2 : 0.2f * e2; wv.z = __expf(e2);
            float e3 = l.w + rn.w; e3 = (e3 > 0.f) ? e3 : 0.2f * e3; wv.w = __expf(e3);
            s_s[w][lane] = s;
            *(float4*)&s_w[w][lane][0] = wv;
        }
        __syncwarp();
        int j = 0;
        for (; j + 4 <= m; j += 4) {
            int   s0 = s_s[w][j],     s1 = s_s[w][j + 1];
            int   s2 = s_s[w][j + 2], s3 = s_s[w][j + 3];
            float a0 = s_w[w][j][head],     a1 = s_w[w][j + 1][head];
            float a2 = s_w[w][j + 2][head], a3 = s_w[w][j + 3][head];
            uint4 h0 = *(const uint4*)(htab + (size_t)s0 * 256);
            uint4 h1 = *(const uint4*)(htab + (size_t)s1 * 256);
            uint4 h2 = *(const uint4*)(htab + (size_t)s2 * 256);
            uint4 h3 = *(const uint4*)(htab + (size_t)s3 * 256);
            #define ACC4(hv, a)                                                   \
            do {                                                                  \
                float2 f0 = __half22float2(*(const __half2*)&(hv).x);             \
                float2 f1 = __half22float2(*(const __half2*)&(hv).y);             \
                float2 f2 = __half22float2(*(const __half2*)&(hv).z);             \
                float2 f3 = __half22float2(*(const __half2*)&(hv).w);             \
                acc[0] += (a) * f0.x; acc[1] += (a) * f0.y;                       \
                acc[2] += (a) * f1.x; acc[3] += (a) * f1.y;                       \
                acc[4] += (a) * f2.x; acc[5] += (a) * f2.y;                       \
                acc[6] += (a) * f3.x; acc[7] += (a) * f3.y;                       \
            } while (0)
            ACC4(h0, a0);
            ACC4(h1, a1);
            ACC4(h2, a2);
            ACC4(h3, a3);
            den += (a0 + a1) + (a2 + a3);
        }
        for (; j < m; j++) {
            int s0 = s_s[w][j];
            float a0 = s_w[w][j][head];
            uint4 h0 = *(const uint4*)(htab + (size_t)s0 * 256);
            ACC4(h0, a0);
            den += a0;
        }
        __syncwarp();
    }

    float inv = 1.f / den;
    float4 b0 = *(const float4*)(bias + lane * 8);
    float4 b1 = *(const float4*)(bias + lane * 8 + 4);
    float v[8];
    v[0] = fmaxf(acc[0] * inv + b0.x, 0.f);
    v[1] = fmaxf(acc[1] * inv + b0.y, 0.f);
    v[2] = fmaxf(acc[2] * inv + b0.z, 0.f);
    v[3] = fmaxf(acc[3] * inv + b0.w, 0.f);
    v[4] = fmaxf(acc[4] * inv + b1.x, 0.f);
    v[5] = fmaxf(acc[5] * inv + b1.y, 0.f);
    v[6] = fmaxf(acc[6] * inv + b1.z, 0.f);
    v[7] = fmaxf(acc[7] * inv + b1.w, 0.f);
    size_t oi = (size_t)n * 256 + lane * 8;
    if (write_f16) {
        uint4 pk;
        *(__half2*)&pk.x = __floats2half2_rn(v[0], v[1]);
        *(__half2*)&pk.y = __floats2half2_rn(v[2], v[3]);
        *(__half2*)&pk.z = __floats2half2_rn(v[4], v[5]);
        *(__half2*)&pk.w = __floats2half2_rn(v[6], v[7]);
        *(uint4*)(g_Ah + oi) = pk;
    } else {
        *(float4*)(outf + oi) = make_float4(v[0], v[1], v[2], v[3]);
        *(float4*)(outf + oi + 4) = make_float4(v[4], v[5], v[6], v[7]);
    }
}

// ---------------- launch ----------------
extern "C" void kernel_launch(void* const* d_in, const int* in_sizes, int n_in,
                              void* d_out, int out_size)
{
    const float* feat = (const float*)d_in[0];
    const int*   src  = (const int*)d_in[1];
    const int*   dst  = (const int*)d_in[2];
    const float* W1   = (const float*)d_in[3];
    const float* al1  = (const float*)d_in[4];
    const float* ar1  = (const float*)d_in[5];
    const float* b1   = (const float*)d_in[6];
    const float* W2   = (const float*)d_in[7];
    const float* al2  = (const float*)d_in[8];
    const float* ar2  = (const float*)d_in[9];
    const float* b2   = (const float*)d_in[10];
    float* out = (float*)d_out;
    int E = in_sizes[1];

    void* p;
    cudaGetSymbolAddress(&p, g_Ah);  __half* ah  = (__half*)p;
    cudaGetSymbolAddress(&p, g_Wt1); __half* wt1 = (__half*)p;
    cudaGetSymbolAddress(&p, g_Wt2); __half* wt2 = (__half*)p;

    static cudaStream_t s2 = nullptr;
    static cudaEvent_t evFork = nullptr, evJoin = nullptr;
    static int init_done = 0;
    if (!init_done) {
        cudaFuncSetAttribute(gemm_mma_kernel,
                             cudaFuncAttributeMaxDynamicSharedMemorySize, GEMM_SMEM);
        cudaStreamCreateWithFlags(&s2, cudaStreamNonBlocking);
        cudaEventCreateWithFlags(&evFork, cudaEventDisableTiming);
        cudaEventCreateWithFlags(&evJoin, cudaEventDisableTiming);
        init_done = 1;
    }

    int egrid = (E + 255) / 256;
    int ngrid = (NN + 255) / 256;
    dim3 ggrid((NN + 127) / 128, 2);

    // fork: CSR build on side stream, concurrent with splits + GEMM-1
    cudaEventRecord(evFork, 0);
    cudaStreamWaitEvent(s2, evFork, 0);
    zero_indeg_kernel<<<ngrid, 256, 0, s2>>>();
    csr_count_kernel<<<egrid, 256, 0, s2>>>(dst, E);
    scan_kernel<<<1, 1024, 0, s2>>>();
    csr_scatter_kernel<<<egrid, 256, 0, s2>>>(dst, src, E);
    cudaEventRecord(evJoin, s2);

    // main stream: feature convert + both weight tables + GEMM-1
    asplit_kernel<<<NN / 2, 256>>>(feat);
    wsplit_kernel<<<256, 256>>>(W1, wt1);
    wsplit_kernel<<<256, 256>>>(W2, wt2);
    gemm_mma_kernel<<<ggrid, 256, GEMM_SMEM>>>(ah, wt1, al1, ar1, NN);

    // join: aggregate needs CSR
    cudaStreamWaitEvent(0, evJoin, 0);
    aggregate_kernel<<<NN / 8, 256>>>(b1, nullptr, 1);

    // layer 2
    gemm_mma_kernel<<<ggrid, 256, GEMM_SMEM>>>(ah, wt2, al2, ar2, NN);
    aggregate_kernel<<<NN / 8, 256>>>(b2, out, 0);
}

// round 12
// speedup vs baseline: 3.3424x; 1.0735x over previous
#include <cuda_runtime.h>
#include <cuda_fp16.h>
#include <cstdint>
#include <cstddef>

#define NN 50000
#define EE 850000
#define HH 4
#define SPLIT 25088                     // = 196*128 = 3136*8

// ---------------- scratch (static device globals; no runtime alloc) ----------
__device__ __half g_hh1[(size_t)NN * 256];    // layer-1 h (fp16 gather table)
__device__ __half g_hh2[(size_t)NN * 256];    // layer-2 h
__device__ float g_el1[NN * HH];
__device__ float g_er1[NN * HH];
__device__ float g_el2[NN * HH];
__device__ float g_er2[NN * HH];
__device__ __align__(16) int g_indeg[NN];
__device__ __align__(16) int g_off[NN + 4];
__device__ __align__(16) int g_cur[NN];
__device__ int   g_csrc[EE];                  // CSR payload: src node id
__device__ __half g_Ah[(size_t)NN * 256];     // GEMM input (fp16)
__device__ __half g_Wt1[256 * 256];           // W1 fp16, transposed [n][k]
__device__ __half g_Wt2[256 * 256];           // W2 fp16, transposed [n][k]

// ---------------- PTX helpers ----------------
__device__ __forceinline__ uint32_t smem_u32(const void* p) {
    uint32_t a;
    asm("{ .reg .u64 t; cvta.to.shared.u64 t, %1; cvt.u32.u64 %0, t; }"
        : "=r"(a) : "l"(p));
    return a;
}
#define CP_ASYNC16(dst, src) \
    asm volatile("cp.async.cg.shared.global [%0], [%1], 16;" :: "r"(dst), "l"(src))
#define CP_COMMIT() asm volatile("cp.async.commit_group;" ::: "memory")
#define CP_WAIT(n)  asm volatile("cp.async.wait_group %0;" :: "n"(n) : "memory")

__device__ __forceinline__ void mma_f16(float* c, const uint32_t* a,
                                        uint32_t b0, uint32_t b1) {
    asm volatile(
        "mma.sync.aligned.m16n8k16.row.col.f32.f16.f16.f32 "
        "{%0,%1,%2,%3}, {%4,%5,%6,%7}, {%8,%9}, {%0,%1,%2,%3};"
        : "+f"(c[0]), "+f"(c[1]), "+f"(c[2]), "+f"(c[3])
        : "r"(a[0]), "r"(a[1]), "r"(a[2]), "r"(a[3]), "r"(b0), "r"(b1));
}
__device__ __forceinline__ void ldm_x4(uint32_t* r, uint32_t addr) {
    asm volatile(
        "ldmatrix.sync.aligned.m8n8.x4.shared.b16 {%0,%1,%2,%3}, [%4];"
        : "=r"(r[0]), "=r"(r[1]), "=r"(r[2]), "=r"(r[3]) : "r"(addr));
}

// ---------------- CSR build ----------------
__global__ void zero_indeg_kernel() {
    int i = blockIdx.x * blockDim.x + threadIdx.x;
    if (i < NN) g_indeg[i] = 0;
}

__global__ void csr_count_kernel(const int* __restrict__ dst, int E) {
    int e = blockIdx.x * blockDim.x + threadIdx.x;
    if (e < E) atomicAdd(&g_indeg[dst[e]], 1);
}

__global__ void scan_kernel() {
    __shared__ int warp_sums[32];
    __shared__ int s_carry;
    int tid = threadIdx.x;
    int lane = tid & 31, wid = tid >> 5;
    if (tid == 0) s_carry = 0;
    __syncthreads();
    const int NQ = NN / 4;
    for (int base = 0; base < NQ; base += 1024) {
        int idx = base + tid;
        int4 v = make_int4(0, 0, 0, 0);
        if (idx < NQ) v = ((const int4*)g_indeg)[idx];
        int tot = v.x + v.y + v.z + v.w;
        int x = tot;
        #pragma unroll
        for (int o = 1; o < 32; o <<= 1) {
            int t = __shfl_up_sync(0xffffffffu, x, o);
            if (lane >= o) x += t;
        }
        if (lane == 31) warp_sums[wid] = x;
        __syncthreads();
        if (wid == 0) {
            int ws = warp_sums[lane];
            #pragma unroll
            for (int o = 1; o < 32; o <<= 1) {
                int t = __shfl_up_sync(0xffffffffu, ws, o);
                if (lane >= o) ws += t;
            }
            warp_sums[lane] = ws;
        }
        __syncthreads();
        int warp_excl = (wid == 0) ? 0 : warp_sums[wid - 1];
        int excl = x - tot + warp_excl + s_carry;
        if (idx < NQ) {
            int4 o;
            o.x = excl;
            o.y = o.x + v.x;
            o.z = o.y + v.y;
            o.w = o.z + v.z;
            ((int4*)g_off)[idx] = o;
            ((int4*)g_cur)[idx] = o;
        }
        __syncthreads();
        if (tid == 0) s_carry += warp_sums[31];
        __syncthreads();
    }
    if (threadIdx.x == 0) g_off[NN] = s_carry;
}

__global__ void csr_scatter_kernel(const int* __restrict__ dst,
                                   const int* __restrict__ src, int E) {
    int e = blockIdx.x * blockDim.x + threadIdx.x;
    if (e < E) {
        int p = atomicAdd(&g_cur[dst[e]], 1);
        g_csrc[p] = src[e];
    }
}

// ---------------- splits ----------------
__global__ void wsplit_kernel(const float* __restrict__ W, __half* __restrict__ Wt) {
    int idx = blockIdx.x * 256 + threadIdx.x;
    int k = idx >> 8, n = idx & 255;
    Wt[n * 256 + k] = __float2half_rn(W[k * 256 + n]);
}

__global__ void asplit_kernel(const float* __restrict__ X, size_t elemOff) {
    size_t i = elemOff + ((size_t)blockIdx.x * 256 + threadIdx.x) * 2;
    float2 v = *(const float2*)(X + i);
    *(__half2*)(g_Ah + i) = __floats2half2_rn(v.x, v.y);
}

// --------- fp16 mma.sync GEMM (single term) + fused attn epilogue ------------
#define SA 40
#define ATILE (128 * SA)
#define BUFB (2 * ATILE * 2)
#define GEMM_SMEM (2 * BUFB)

__global__ __launch_bounds__(256) void gemm_mma_kernel(
    const __half* __restrict__ A, const __half* __restrict__ Wt,
    const float* __restrict__ al, const float* __restrict__ ar,
    __half* __restrict__ hh_out, float* __restrict__ el_out,
    float* __restrict__ er_out, int rowOff, int nrows)
{
    extern __shared__ __half sm[];
    int tid = threadIdx.x;
    int lane = tid & 31;
    int wid = tid >> 5;
    int wm = wid & 3, wn = wid >> 2;
    int g = lane >> 2, t = lane & 3;
    int rowBase = rowOff + blockIdx.x * 128;
    int nbase = blockIdx.y * 128;

    uint32_t sb = smem_u32(sm);

    uint32_t aOff = (uint32_t)(((wm * 32 + (lane & 15)) * SA + ((lane >> 4) << 3)) * 2);
    uint32_t bOff = (uint32_t)(((wn * 64 + ((lane >> 4) << 3) + (lane & 7)) * SA +
                                (((lane >> 3) & 1) << 3)) * 2);

    float acc[2][8][4];
    #pragma unroll
    for (int mt = 0; mt < 2; mt++)
        #pragma unroll
        for (int nt = 0; nt < 8; nt++)
            #pragma unroll
            for (int q = 0; q < 4; q++) acc[mt][nt][q] = 0.f;

    #define STAGE(buf, k0)                                                        \
    do {                                                                          \
        uint32_t base = sb + (uint32_t)(buf) * BUFB;                              \
        _Pragma("unroll")                                                         \
        for (int p = 0; p < 2; p++) {                                             \
            int c = tid + p * 256;                                                \
            int r = c >> 2, j = c & 3;                                            \
            uint32_t so = (uint32_t)(r * (SA * 2) + j * 16);                      \
            int arow = rowBase + r;                                               \
            if (arow < nrows)                                                     \
                CP_ASYNC16(base + so, A + (size_t)arow * 256 + (k0) + j * 8);     \
            CP_ASYNC16(base + ATILE * 2 + so,                                     \
                       Wt + (size_t)(nbase + r) * 256 + (k0) + j * 8);            \
        }                                                                         \
        CP_COMMIT();                                                              \
    } while (0)

    STAGE(0, 0);

    #pragma unroll
    for (int kt = 0; kt < 8; kt++) {
        if (kt < 7) STAGE((kt + 1) & 1, (kt + 1) * 32);
        if (kt < 7) { CP_WAIT(1); } else { CP_WAIT(0); }
        __syncthreads();

        uint32_t bufb = sb + (uint32_t)(kt & 1) * BUFB;
        uint32_t aP = bufb + aOff;
        uint32_t bP = bufb + ATILE * 2 + bOff;

        #pragma unroll
        for (int kk = 0; kk < 2; kk++) {
            uint32_t ksb = (uint32_t)(kk * 32);
            uint32_t ah[2][4];
            #pragma unroll
            for (int mt = 0; mt < 2; mt++)
                ldm_x4(ah[mt], aP + (uint32_t)(mt * 16 * SA * 2) + ksb);
            #pragma unroll
            for (int p = 0; p < 4; p++) {
                uint32_t bh[4];
                ldm_x4(bh, bP + (uint32_t)(p * 16 * SA * 2) + ksb);
                #pragma unroll
                for (int sub = 0; sub < 2; sub++) {
                    int nt = p * 2 + sub;
                    #pragma unroll
                    for (int mt = 0; mt < 2; mt++)
                        mma_f16(acc[mt][nt], ah[mt], bh[2 * sub], bh[2 * sub + 1]);
                }
            }
        }
        __syncthreads();
    }

    // ---- epilogue: write h fp16 + fused el/er ----
    int head = blockIdx.y * 2 + wn;
    float2 alv[8], arv[8];
    #pragma unroll
    for (int nt = 0; nt < 8; nt++) {
        int d = nt * 8 + 2 * t;
        alv[nt] = *(const float2*)(al + head * 64 + d);
        arv[nt] = *(const float2*)(ar + head * 64 + d);
    }

    #pragma unroll
    for (int mt = 0; mt < 2; mt++) {
        int r0 = rowBase + wm * 32 + mt * 16 + g;
        int r1 = r0 + 8;
        float el0 = 0.f, er0 = 0.f, el1 = 0.f, er1 = 0.f;
        #pragma unroll
        for (int nt = 0; nt < 8; nt++) {
            int col = nbase + wn * 64 + nt * 8 + 2 * t;
            if (r0 < nrows)
                *(__half2*)(hh_out + (size_t)r0 * 256 + col) =
                    __floats2half2_rn(acc[mt][nt][0], acc[mt][nt][1]);
            if (r1 < nrows)
                *(__half2*)(hh_out + (size_t)r1 * 256 + col) =
                    __floats2half2_rn(acc[mt][nt][2], acc[mt][nt][3]);
            el0 += acc[mt][nt][0] * alv[nt].x + acc[mt][nt][1] * alv[nt].y;
            er0 += acc[mt][nt][0] * arv[nt].x + acc[mt][nt][1] * arv[nt].y;
            el1 += acc[mt][nt][2] * alv[nt].x + acc[mt][nt][3] * alv[nt].y;
            er1 += acc[mt][nt][2] * arv[nt].x + acc[mt][nt][3] * arv[nt].y;
        }
        #pragma unroll
        for (int o = 1; o < 4; o <<= 1) {
            el0 += __shfl_xor_sync(0xffffffffu, el0, o);
            er0 += __shfl_xor_sync(0xffffffffu, er0, o);
            el1 += __shfl_xor_sync(0xffffffffu, el1, o);
            er1 += __shfl_xor_sync(0xffffffffu, er1, o);
        }
        if (t == 0) {
            if (r0 < nrows) { el_out[r0 * 4 + head] = el0; er_out[r0 * 4 + head] = er0; }
            if (r1 < nrows) { el_out[r1 * 4 + head] = el1; er_out[r1 * 4 + head] = er1; }
        }
    }
}

// ---------- warp-per-node edge-softmax + aggregation (16B/lane gathers) ------
__global__ __launch_bounds__(256) void aggregate_kernel(
    const __half* __restrict__ hh, const float* __restrict__ el,
    const float* __restrict__ er, const float* __restrict__ bias,
    float* __restrict__ outf, int write_f16, int nodeOff)
{
    __shared__ float s_w[8][32][4];
    __shared__ int   s_s[8][32];
    int w = threadIdx.x >> 5, lane = threadIdx.x & 31;
    int n = nodeOff + blockIdx.x * 8 + w;
    int beg = g_off[n], end = g_off[n + 1];
    int head = lane >> 3;

    float4 rn = ((const float4*)er)[n];
    float acc[8];
    #pragma unroll
    for (int k = 0; k < 8; k++) acc[k] = 0.f;
    float den = 0.f;
    const __half* htab = hh + (size_t)lane * 8;

    for (int base = beg; base < end; base += 32) {
        int m = end - base;
        if (m > 32) m = 32;
        if (lane < m) {
            int s = g_csrc[base + lane];
            float4 l = ((const float4*)el)[s];
            float4 wv;
            float e0 = l.x + rn.x; e0 = (e0 > 0.f) ? e0 : 0.2f * e0; wv.x = __expf(e0);
            float e1 = l.y + rn.y; e1 = (e1 > 0.f) ? e1 : 0.2f * e1; wv.y = __expf(e1);
            float e2 = l.z + rn.z; e2 = (e2 > 0.f) ? e2 : 0.2f * e2; wv.z = __expf(e2);
            float e3 = l.w + rn.w; e3 = (e3 > 0.f) ? e3 : 0.2f * e3; wv.w = __expf(e3);
            s_s[w][lane] = s;
            *(float4*)&s_w[w][lane][0] = wv;
        }
        __syncwarp();
        int j = 0;
        for (; j + 4 <= m; j += 4) {
            int   s0 = s_s[w][j],     s1 = s_s[w][j + 1];
            int   s2 = s_s[w][j + 2], s3 = s_s[w][j + 3];
            float a0 = s_w[w][j][head],     a1 = s_w[w][j + 1][head];
            float a2 = s_w[w][j + 2][head], a3 = s_w[w][j + 3][head];
            uint4 h0 = *(const uint4*)(htab + (size_t)s0 * 256);
            uint4 h1 = *(const uint4*)(htab + (size_t)s1 * 256);
            uint4 h2 = *(const uint4*)(htab + (size_t)s2 * 256);
            uint4 h3 = *(const uint4*)(htab + (size_t)s3 * 256);
            #define ACC4(hv, a)                                                   \
            do {                                                                  \
                float2 f0 = __half22float2(*(const __half2*)&(hv).x);             \
                float2 f1 = __half22float2(*(const __half2*)&(hv).y);             \
                float2 f2 = __half22float2(*(const __half2*)&(hv).z);             \
                float2 f3 = __half22float2(*(const __half2*)&(hv).w);             \
                acc[0] += (a) * f0.x; acc[1] += (a) * f0.y;                       \
                acc[2] += (a) * f1.x; acc[3] += (a) * f1.y;                       \
                acc[4] += (a) * f2.x; acc[5] += (a) * f2.y;                       \
                acc[6] += (a) * f3.x; acc[7] += (a) * f3.y;                       \
            } while (0)
            ACC4(h0, a0);
            ACC4(h1, a1);
            ACC4(h2, a2);
            ACC4(h3, a3);
            den += (a0 + a1) + (a2 + a3);
        }
        for (; j < m; j++) {
            int s0 = s_s[w][j];
            float a0 = s_w[w][j][head];
            uint4 h0 = *(const uint4*)(htab + (size_t)s0 * 256);
            ACC4(h0, a0);
            den += a0;
        }
        __syncwarp();
    }

    float inv = 1.f / den;
    float4 b0 = *(const float4*)(bias + lane * 8);
    float4 b1 = *(const float4*)(bias + lane * 8 + 4);
    float v[8];
    v[0] = fmaxf(acc[0] * inv + b0.x, 0.f);
    v[1] = fmaxf(acc[1] * inv + b0.y, 0.f);
    v[2] = fmaxf(acc[2] * inv + b0.z, 0.f);
    v[3] = fmaxf(acc[3] * inv + b0.w, 0.f);
    v[4] = fmaxf(acc[4] * inv + b1.x, 0.f);
    v[5] = fmaxf(acc[5] * inv + b1.y, 0.f);
    v[6] = fmaxf(acc[6] * inv + b1.z, 0.f);
    v[7] = fmaxf(acc[7] * inv + b1.w, 0.f);
    size_t oi = (size_t)n * 256 + lane * 8;
    if (write_f16) {
        uint4 pk;
        *(__half2*)&pk.x = __floats2half2_rn(v[0], v[1]);
        *(__half2*)&pk.y = __floats2half2_rn(v[2], v[3]);
        *(__half2*)&pk.z = __floats2half2_rn(v[4], v[5]);
        *(__half2*)&pk.w = __floats2half2_rn(v[6], v[7]);
        *(uint4*)(g_Ah + oi) = pk;
    } else {
        *(float4*)(outf + oi) = make_float4(v[0], v[1], v[2], v[3]);
        *(float4*)(outf + oi + 4) = make_float4(v[4], v[5], v[6], v[7]);
    }
}

// ---------------- launch ----------------
extern "C" void kernel_launch(void* const* d_in, const int* in_sizes, int n_in,
                              void* d_out, int out_size)
{
    const float* feat = (const float*)d_in[0];
    const int*   src  = (const int*)d_in[1];
    const int*   dst  = (const int*)d_in[2];
    const float* W1   = (const float*)d_in[3];
    const float* al1  = (const float*)d_in[4];
    const float* ar1  = (const float*)d_in[5];
    const float* b1   = (const float*)d_in[6];
    const float* W2   = (const float*)d_in[7];
    const float* al2  = (const float*)d_in[8];
    const float* ar2  = (const float*)d_in[9];
    const float* b2   = (const float*)d_in[10];
    float* out = (float*)d_out;
    int E = in_sizes[1];

    void* p;
    cudaGetSymbolAddress(&p, g_Ah);  __half* ah  = (__half*)p;
    cudaGetSymbolAddress(&p, g_Wt1); __half* wt1 = (__half*)p;
    cudaGetSymbolAddress(&p, g_Wt2); __half* wt2 = (__half*)p;
    cudaGetSymbolAddress(&p, g_hh1); __half* hh1 = (__half*)p;
    cudaGetSymbolAddress(&p, g_hh2); __half* hh2 = (__half*)p;
    cudaGetSymbolAddress(&p, g_el1); float* el1 = (float*)p;
    cudaGetSymbolAddress(&p, g_er1); float* er1 = (float*)p;
    cudaGetSymbolAddress(&p, g_el2); float* el2 = (float*)p;
    cudaGetSymbolAddress(&p, g_er2); float* er2 = (float*)p;

    static cudaStream_t s2 = nullptr, s3 = nullptr;
    static cudaEvent_t evFork = nullptr, evJoin = nullptr;
    static cudaEvent_t evG1 = nullptr, evB = nullptr, evAsb = nullptr;
    static int init_done = 0;
    if (!init_done) {
        cudaFuncSetAttribute(gemm_mma_kernel,
                             cudaFuncAttributeMaxDynamicSharedMemorySize, GEMM_SMEM);
        cudaStreamCreateWithFlags(&s2, cudaStreamNonBlocking);
        cudaStreamCreateWithFlags(&s3, cudaStreamNonBlocking);
        cudaEventCreateWithFlags(&evFork, cudaEventDisableTiming);
        cudaEventCreateWithFlags(&evJoin, cudaEventDisableTiming);
        cudaEventCreateWithFlags(&evG1, cudaEventDisableTiming);
        cudaEventCreateWithFlags(&evB, cudaEventDisableTiming);
        cudaEventCreateWithFlags(&evAsb, cudaEventDisableTiming);
        init_done = 1;
    }

    int egrid = (E + 255) / 256;
    int ngrid = (NN + 255) / 256;
    dim3 gfull((NN + 127) / 128, 2);            // 391
    dim3 ga(SPLIT / 128, 2);                    // 196
    dim3 gb((NN - SPLIT + 127) / 128, 2);       // 195
    const int ASPLIT_A = SPLIT * 256 / 512;     // 12544 blocks
    const int ASPLIT_B = (NN - SPLIT) * 256 / 512; // 12456 blocks

    cudaEventRecord(evFork, 0);
    // s2: CSR build (overlaps splits + GEMM-1)
    cudaStreamWaitEvent(s2, evFork, 0);
    zero_indeg_kernel<<<ngrid, 256, 0, s2>>>();
    csr_count_kernel<<<egrid, 256, 0, s2>>>(dst, E);
    scan_kernel<<<1, 1024, 0, s2>>>();
    csr_scatter_kernel<<<egrid, 256, 0, s2>>>(dst, src, E);
    cudaEventRecord(evJoin, s2);

    // s3: second half of feature convert
    cudaStreamWaitEvent(s3, evFork, 0);
    asplit_kernel<<<ASPLIT_B, 256, 0, s3>>>(feat, (size_t)SPLIT * 256);
    cudaEventRecord(evAsb, s3);

    // s0: weight tables + first half convert + GEMM-1 (full)
    wsplit_kernel<<<256, 256>>>(W1, wt1);
    wsplit_kernel<<<256, 256>>>(W2, wt2);
    asplit_kernel<<<ASPLIT_A, 256>>>(feat, 0);
    cudaStreamWaitEvent(0, evAsb, 0);
    gemm_mma_kernel<<<gfull, 256, GEMM_SMEM>>>(ah, wt1, al1, ar1,
                                               hh1, el1, er1, 0, NN);
    cudaEventRecord(evG1, 0);

    // s2: agg1b (nodes >= SPLIT) after CSR (same stream) + GEMM-1
    cudaStreamWaitEvent(s2, evG1, 0);
    aggregate_kernel<<<(NN - SPLIT) / 8, 256, 0, s2>>>(
        hh1, el1, er1, b1, nullptr, 1, SPLIT);
    cudaEventRecord(evB, s2);

    // s0: agg1a then gemm2a (rows < SPLIT) — overlaps agg1b on s2
    cudaStreamWaitEvent(0, evJoin, 0);
    aggregate_kernel<<<SPLIT / 8, 256>>>(hh1, el1, er1, b1, nullptr, 1, 0);
    gemm_mma_kernel<<<ga, 256, GEMM_SMEM>>>(ah, wt2, al2, ar2,
                                            hh2, el2, er2, 0, NN);
    // s0: gemm2b after agg1b, then final aggregate
    cudaStreamWaitEvent(0, evB, 0);
    gemm_mma_kernel<<<gb, 256, GEMM_SMEM>>>(ah, wt2, al2, ar2,
                                            hh2, el2, er2, SPLIT, NN);
    aggregate_kernel<<<NN / 8, 256>>>(hh2, el2, er2, b2, out, 0, 0);
}